// round 12
// baseline (speedup 1.0000x reference)
#include <cuda_runtime.h>
#include <cuda_fp16.h>
#include <cstdint>

#define NTOK  50257
#define NIN   300
#define KPAD  320
#define TT    18
#define BATCH 4096
#define NCAP  (BATCH * TT)
#define NBLK  197              // ceil(NTOK/256)

typedef unsigned long long ull;

// ---------------- device scratch (no allocations allowed) ----------------
__device__ float   g_EW [(size_t)NTOK * 512];   // [slot][dir*256 + gate*64 + kk]
__device__ __half  g_Wh [(size_t)512 * KPAD];   // [n][k], fp16
__device__ int g_flag[NTOK];    // generation-stamped presence flags
__device__ int g_list[NTOK];
__device__ int g_slot[NTOK];
__device__ int g_count;
__device__ int g_gen;           // increments once per kernel_launch (in lstm)

// ---------------- activation helpers ----------------
__device__ __forceinline__ float tanha(float x){
    float r; asm("tanh.approx.f32 %0, %1;" : "=f"(r) : "f"(x)); return r;
}
__device__ __forceinline__ float sigmt(float x){   // 0.5 + 0.5*tanh(x/2)
    return fmaf(tanha(x * 0.5f), 0.5f, 0.5f);
}

// ---------------- mma.sync / cp.async helpers ----------------
__device__ __forceinline__ uint32_t smem_u32(const void* p){
    uint32_t a; asm("{ .reg .u64 t; cvta.to.shared.u64 t, %1; cvt.u32.u64 %0, t; }" : "=r"(a) : "l"(p));
    return a;
}
__device__ __forceinline__ void ldm4(uint32_t (&r)[4], uint32_t addr){
    asm volatile("ldmatrix.sync.aligned.m8n8.x4.shared.b16 {%0,%1,%2,%3}, [%4];"
        : "=r"(r[0]), "=r"(r[1]), "=r"(r[2]), "=r"(r[3]) : "r"(addr));
}
__device__ __forceinline__ void ldm2(uint32_t& r0, uint32_t& r1, uint32_t addr){
    asm volatile("ldmatrix.sync.aligned.m8n8.x2.shared.b16 {%0,%1}, [%2];"
        : "=r"(r0), "=r"(r1) : "r"(addr));
}
__device__ __forceinline__ void mma16816(float (&c)[4], const uint32_t (&a)[4],
                                         uint32_t b0, uint32_t b1){
    asm volatile(
        "mma.sync.aligned.m16n8k16.row.col.f32.f16.f16.f32 "
        "{%0,%1,%2,%3}, {%4,%5,%6,%7}, {%8,%9}, {%0,%1,%2,%3};"
        : "+f"(c[0]), "+f"(c[1]), "+f"(c[2]), "+f"(c[3])
        : "r"(a[0]), "r"(a[1]), "r"(a[2]), "r"(a[3]), "r"(b0), "r"(b1));
}
__device__ __forceinline__ uint32_t pk2h(__half a, __half b){
    return (uint32_t)__half_as_ushort(a) | ((uint32_t)__half_as_ushort(b) << 16);
}
#define CP16(sa, gp)  asm volatile("cp.async.cg.shared.global [%0], [%1], 16;" :: "r"(sa), "l"(gp))
#define CP_COMMIT()   asm volatile("cp.async.commit_group;" ::: "memory")
#define CP_WAIT0()    asm volatile("cp.async.wait_group 0;" ::: "memory")

// ============================================================================
// dd_markw / dd_compact: generation-stamped token dedup (+ W fp16 convert)
// ============================================================================
__global__ void dd_markw(const int* __restrict__ cap,
                         const float* __restrict__ Wf, const float* __restrict__ Wb){
    const int idx = blockIdx.x * 256 + threadIdx.x;
    const int gen = g_gen + 1;
    if (idx < NCAP) g_flag[cap[idx]] = gen;
    if (idx == 0)   g_count = 0;
    if (idx < 512 * KPAD){
        const int n = idx / KPAD, k = idx % KPAD;
        float v = 0.f;
        if (k < NIN) v = (n < 256) ? Wf[(size_t)k * 256 + n] : Wb[(size_t)k * 256 + (n - 256)];
        g_Wh[(size_t)n * KPAD + k] = __float2half_rn(v);
    }
}
__global__ void dd_compact(){
    const int i = blockIdx.x * 256 + threadIdx.x;
    const int gen = g_gen + 1;
    if (i < NTOK && g_flag[i] == gen){
        int pos = atomicAdd(&g_count, 1);
        g_list[pos] = i;
        g_slot[i]   = pos;
    }
}

// ============================================================================
// gemm_tc (known-good 98.4us): CTA 128x128, A = Ehi+Elo fp16, B = W fp16.
// ============================================================================
#define KT          10
#define MAT_BYTES   10240
#define STAGE_BYTES 30720
#define G_SMEM      (2 * STAGE_BYTES)

__global__ void __launch_bounds__(256, 2) gemm_tc(const float* __restrict__ E)
{
    const int cnt = g_count;
    const int m0  = blockIdx.y * 128;
    if (m0 >= cnt) return;

    extern __shared__ char sm[];
    const uint32_t smb = smem_u32(sm);
    const int tid = threadIdx.x, lane = tid & 31, wid = tid >> 5;
    const int slab = blockIdx.x;
    const int warp_m = (wid >> 2) * 64;
    const int warp_n = (wid & 3) * 32;

    const int erow = tid >> 1, eh = tid & 1;
    const int wn   = tid >> 1, wc = tid & 1;
    const int gm   = m0 + erow;
    const int tokE = (gm < cnt) ? g_list[gm] : g_list[0];
    const float* Ebase = E + (size_t)tokE * NIN;
    const __half* WHb  = g_Wh + (size_t)(slab * 128 + wn) * KPAD;

    float4 eR[4]; uint4 wR[2];

    auto LDGT = [&](int kt){
        const int k0 = kt * 32;
        #pragma unroll
        for (int j = 0; j < 4; j++){
            const int k = k0 + eh * 16 + j * 4;
            eR[j] = (k < NIN) ? *(const float4*)(Ebase + k)
                              : make_float4(0.f, 0.f, 0.f, 0.f);
        }
        wR[0] = *(const uint4*)(WHb + k0 + wc * 16);
        wR[1] = *(const uint4*)(WHb + k0 + wc * 16 + 8);
    };
    auto STST = [&](int s){
        char* base = sm + s * STAGE_BYTES;
        #pragma unroll
        for (int j = 0; j < 4; j++){
            const float4 v = eR[j];
            const __half hx = __float2half_rn(v.x), hy = __float2half_rn(v.y);
            const __half hz = __float2half_rn(v.z), hw = __float2half_rn(v.w);
            const float lx = v.x - __half2float(hx), ly = v.y - __half2float(hy);
            const float lz = v.z - __half2float(hz), lw = v.w - __half2float(hw);
            const int koff = eh * 16 + j * 4;
            *(uint2*)(base + erow * 80 + koff * 2) =
                make_uint2(pk2h(hx, hy), pk2h(hz, hw));
            *(uint2*)(base + MAT_BYTES + erow * 80 + koff * 2) =
                make_uint2(pk2h(__float2half_rn(lx), __float2half_rn(ly)),
                           pk2h(__float2half_rn(lz), __float2half_rn(lw)));
        }
        *(uint4*)(base + 2*MAT_BYTES + wn * 80 + wc * 32)      = wR[0];
        *(uint4*)(base + 2*MAT_BYTES + wn * 80 + wc * 32 + 16) = wR[1];
    };

    float acc[4][4][4];
    #pragma unroll
    for (int a = 0; a < 4; a++)
        #pragma unroll
        for (int b = 0; b < 4; b++)
            #pragma unroll
            for (int r = 0; r < 4; r++) acc[a][b][r] = 0.f;

    const int aR = warp_m + (lane & 15);
    const int aC = (lane >> 4) * 8;
    const int bR = warp_n + (lane & 7) + ((lane >> 4) << 3);
    const int bC = ((lane >> 3) & 1) * 8;

    LDGT(0); STST(0); __syncthreads();

    #pragma unroll 1
    for (int kt = 0; kt < KT; ++kt){
        if (kt + 1 < KT) LDGT(kt + 1);
        const uint32_t sb = smb + (kt & 1) * STAGE_BYTES;

        auto DOKB = [&](int kb){
            uint32_t ah[4][4], al[4][4];
            #pragma unroll
            for (int fm = 0; fm < 4; fm++){
                ldm4(ah[fm], sb + (aR + fm*16) * 80 + (aC + kb) * 2);
                ldm4(al[fm], sb + MAT_BYTES + (aR + fm*16) * 80 + (aC + kb) * 2);
            }
            uint32_t bh[4][2];
            #pragma unroll
            for (int g = 0; g < 2; g++){
                uint32_t t[4];
                ldm4(t, sb + 2*MAT_BYTES + (bR + g*16) * 80 + (bC + kb) * 2);
                bh[2*g][0] = t[0]; bh[2*g][1] = t[1]; bh[2*g+1][0] = t[2]; bh[2*g+1][1] = t[3];
            }
            #pragma unroll
            for (int fm = 0; fm < 4; fm++)
                #pragma unroll
                for (int fn = 0; fn < 4; fn++){
                    mma16816(acc[fm][fn], ah[fm], bh[fn][0], bh[fn][1]);
                    mma16816(acc[fm][fn], al[fm], bh[fn][0], bh[fn][1]);
                }
        };
        DOKB(0);
        if (kt < KT - 1) DOKB(16);

        if (kt + 1 < KT) STST((kt + 1) & 1);
        __syncthreads();
    }

    const int rBase = m0 + warp_m + (lane >> 2);
    const int cBase = slab * 128 + warp_n + (lane & 3) * 2;
    #pragma unroll
    for (int fm = 0; fm < 4; fm++)
        #pragma unroll
        for (int fn = 0; fn < 4; fn++){
            const int r0 = rBase + fm * 16;
            const int cc = cBase + fn * 8;
            if (r0 < cnt)
                *(float2*)&g_EW[(size_t)r0 * 512 + cc] =
                    make_float2(acc[fm][fn][0], acc[fm][fn][1]);
            if (r0 + 8 < cnt)
                *(float2*)&g_EW[(size_t)(r0 + 8) * 512 + cc] =
                    make_float2(acc[fm][fn][2], acc[fm][fn][3]);
        }
}

// ============================================================================
// LSTM v10 — tensor-core recurrence; cp.async EW prefetch issued at TOP of
// step s for step s+1 (full-step overlap window >> DRAM latency).
// ============================================================================
#define HP      72
#define UTH_OFF 0
#define UTL_OFF 36864
#define H_OFF   73728
#define H_PL    (64 * HP * 2)
#define TOK_OFF (H_OFF + 4 * H_PL)              // 110592
#define EW1_OFF (TOK_OFF + 64 * TT * 4)         // 115200
#define EW_BYTES 65536                          // 8 chunks x 8192
#define L_SMEM  (EW1_OFF + EW_BYTES)            // 180736

__global__ void __launch_bounds__(256, 1) lstm_fused(
    const int*   __restrict__ cap,
    const float* __restrict__ h0f, const float* __restrict__ c0f,
    const float* __restrict__ h0b, const float* __restrict__ c0b,
    const float* __restrict__ Uf,  const float* __restrict__ bf,
    const float* __restrict__ Ub,  const float* __restrict__ bb,
    float* __restrict__ out)
{
    extern __shared__ char sm[];
    const uint32_t smb = smem_u32(sm);
    __half* UTH = (__half*)(sm + UTH_OFF);
    __half* UTL = (__half*)(sm + UTL_OFF);
    int (*toks)[TT] = (int(*)[TT])(sm + TOK_OFF);

    const int dir = blockIdx.y;
    const float* U  = dir ? Ub  : Uf;
    const float* bv = dir ? bb  : bf;
    const float* h0 = dir ? h0b : h0f;
    const float* c0 = dir ? c0b : c0f;
    const int b0   = blockIdx.x * 64;
    const int tid  = threadIdx.x;
    const int lane = tid & 31;
    const int w    = tid >> 5;

    // ---- prologue: U^T hi/lo, tokens, h0 ----
    for (int idx = tid; idx < 64 * 256; idx += 256){
        const int kk = idx >> 8, n = idx & 255;
        const float v = U[kk * 256 + n];
        const __half hi = __float2half_rn(v);
        UTH[n * HP + kk] = hi;
        UTL[n * HP + kk] = __float2half_rn(v - __half2float(hi));
    }
    for (int idx = tid; idx < 64 * TT; idx += 256)
        toks[idx / TT][idx % TT] = g_slot[cap[b0 * TT + idx]];
    {
        __half* Hhi = (__half*)(sm + H_OFF);
        __half* Hlo = (__half*)(sm + H_OFF + H_PL);
        for (int idx = tid; idx < 64 * 64; idx += 256){
            const int r = idx >> 6, kk = idx & 63;
            const float v = h0[(size_t)(b0 + r) * 64 + kk];
            const __half hi = __float2half_rn(v);
            Hhi[r * HP + kk] = hi;
            Hlo[r * HP + kk] = __float2half_rn(v - __half2float(hi));
        }
    }

    const int kkg = w * 8 + (lane & 3) * 2;
    float c[16];
    #pragma unroll
    for (int m = 0; m < 4; m++)
        #pragma unroll
        for (int r = 0; r < 2; r++)
            #pragma unroll
            for (int j = 0; j < 2; j++){
                const int row = m * 16 + (lane >> 2) + r * 8;
                c[m*4 + r*2 + j] = c0[(size_t)(b0 + row) * 64 + kkg + j];
            }
    float bias[4][2];
    #pragma unroll
    for (int g = 0; g < 4; g++){
        bias[g][0] = bv[g * 64 + kkg];
        bias[g][1] = bv[g * 64 + kkg + 1];
    }
    __syncthreads();

    // ---- U fragments: register-resident; UTH/UTL smem dead afterwards ----
    uint32_t uh[4][4][2], ul[4][4][2];
    #pragma unroll
    for (int g = 0; g < 4; g++)
        #pragma unroll
        for (int kt = 0; kt < 4; kt++){
            const uint32_t off =
                (uint32_t)((g*64 + w*8 + (lane & 7)) * HP + kt*16 + ((lane >> 3) & 1) * 8) * 2;
            ldm2(uh[g][kt][0], uh[g][kt][1], smb + UTH_OFF + off);
            ldm2(ul[g][kt][0], ul[g][kt][1], smb + UTL_OFF + off);
        }
    __syncthreads();                 // frags read; EW buf0 may now overwrite UTH/UTL

    // EW prefetch: thread = (row = tid>>2, gate q = tid&3), 16x cp.async 16B.
    const int prow = tid >> 2, pq = tid & 3;
    auto PREF = [&](int snext){
        const int t2 = dir ? (TT - 1 - snext) : snext;
        const uint32_t dstb = smb + (((snext & 1)) ? EW1_OFF : 0);
        const int slot = toks[prow][t2];
        const float* src = g_EW + (size_t)slot * 512 + dir * 256 + pq * 64;
        const uint32_t d0 = dstb + prow * 128 + pq * 32;
        #pragma unroll
        for (int i = 0; i < 16; i++)
            CP16(d0 + (i >> 1) * 8192 + (i & 1) * 16, src + i * 4);
        CP_COMMIT();
    };
    PREF(0);

    const size_t sent_off = (size_t)BATCH * 128 * TT;
    const int aR = lane & 15;
    const int aC = (lane >> 4) * 8;
    float hprev[16];

    for (int s = 0; s < TT; ++s){
        CP_WAIT0();                  // PREF(s) data arrived
        __syncthreads();             // + prev h stores + buf p^1 readers retired
        const int t = dir ? (TT - 1 - s) : s;
        const int p = s & 1;

        // issue NEXT step's prefetch NOW — overlap window = entire step
        if (s + 1 < TT) PREF(s + 1);

        const uint32_t hHi = smb + H_OFF + (p*2 + 0) * H_PL;
        const uint32_t hLo = smb + H_OFF + (p*2 + 1) * H_PL;
        const char* ebase0 = sm + (p ? EW1_OFF : 0) + (size_t)w * 8192 + (lane & 3) * 8;

        // acc init from prefetched smem EW + bias
        float acc[4][4][4];
        #pragma unroll
        for (int m = 0; m < 4; m++){
            #pragma unroll
            for (int r = 0; r < 2; r++){
                const int row = m * 16 + (lane >> 2) + r * 8;
                const char* eb = ebase0 + row * 128;
                #pragma unroll
                for (int g = 0; g < 4; g++){
                    const float2 e = *(const float2*)(eb + g * 32);
                    acc[m][g][r*2 + 0] = e.x + bias[g][0];
                    acc[m][g][r*2 + 1] = e.y + bias[g][1];
                }
            }
        }

        // z += h @ U  (3-term tensor-core)
        #pragma unroll
        for (int kt = 0; kt < 4; kt++){
            uint32_t ahi[4][4], alo[4][4];
            #pragma unroll
            for (int m = 0; m < 4; m++){
                const uint32_t off = (uint32_t)((aR + m*16) * HP + aC + kt*16) * 2;
                ldm4(ahi[m], hHi + off);
                ldm4(alo[m], hLo + off);
            }
            #pragma unroll
            for (int m = 0; m < 4; m++)
                #pragma unroll
                for (int g = 0; g < 4; g++){
                    mma16816(acc[m][g], ahi[m], uh[g][kt][0], uh[g][kt][1]);
                    mma16816(acc[m][g], alo[m], uh[g][kt][0], uh[g][kt][1]);
                    mma16816(acc[m][g], ahi[m], ul[g][kt][0], ul[g][kt][1]);
                }
        }

        // epilogue
        const uint32_t nHi = smb + H_OFF + ((p^1)*2 + 0) * H_PL;
        const uint32_t nLo = smb + H_OFF + ((p^1)*2 + 1) * H_PL;
        #pragma unroll
        for (int m = 0; m < 4; m++){
            #pragma unroll
            for (int r = 0; r < 2; r++){
                const int row = m * 16 + (lane >> 2) + r * 8;
                float hv[2];
                #pragma unroll
                for (int j = 0; j < 2; j++){
                    const int e = r*2 + j;
                    const float ig = sigmt(acc[m][0][e]);
                    const float fg = sigmt(acc[m][1][e]);
                    const float gg = tanha(acc[m][2][e]);
                    const float og = sigmt(acc[m][3][e]);
                    const float cn = fg * c[m*4 + e] + ig * gg;
                    c[m*4 + e] = cn;
                    hv[j] = og * tanha(cn);

                    if (s == TT - 1)
                        out[sent_off + (size_t)(b0 + row) * 128 + dir*64 + kkg + j] = hv[j];

                    if (s & 1){
                        const int tlo = dir ? t : t - 1;
                        const float2 v = dir ? make_float2(hv[j], hprev[m*4 + e])
                                             : make_float2(hprev[m*4 + e], hv[j]);
                        *(float2*)&out[(size_t)(b0 + row) * (128*TT)
                                       + (dir*64 + kkg + j) * TT + tlo] = v;
                    } else {
                        hprev[m*4 + e] = hv[j];
                    }
                }
                const __half h0h = __float2half_rn(hv[0]);
                const __half h1h = __float2half_rn(hv[1]);
                const __half l0h = __float2half_rn(hv[0] - __half2float(h0h));
                const __half l1h = __float2half_rn(hv[1] - __half2float(h1h));
                const uint32_t soff = (uint32_t)(row * HP + kkg) * 2;
                *(uint32_t*)(sm + (nHi - smb) + soff) = pk2h(h0h, h1h);
                *(uint32_t*)(sm + (nLo - smb) + soff) = pk2h(l0h, l1h);
            }
        }
    }

    if (tid == 0 && blockIdx.x == 0 && blockIdx.y == 0)
        g_gen += 1;
}

// ============================================================================
extern "C" void kernel_launch(void* const* d_in, const int* in_sizes, int n_in,
                              void* d_out, int out_size)
{
    const int*   captions = (const int*)  d_in[0];
    const float* h0f = (const float*)d_in[2];
    const float* c0f = (const float*)d_in[3];
    const float* h0b = (const float*)d_in[4];
    const float* c0b = (const float*)d_in[5];
    const float* E   = (const float*)d_in[6];
    const float* Wf  = (const float*)d_in[7];
    const float* Uf  = (const float*)d_in[8];
    const float* bf  = (const float*)d_in[9];
    const float* Wb  = (const float*)d_in[10];
    const float* Ub  = (const float*)d_in[11];
    const float* bb  = (const float*)d_in[12];
    float* out = (float*)d_out;

    cudaFuncSetAttribute(gemm_tc,    cudaFuncAttributeMaxDynamicSharedMemorySize, G_SMEM);
    cudaFuncSetAttribute(lstm_fused, cudaFuncAttributeMaxDynamicSharedMemorySize, L_SMEM);

    // launch index:   0          1           2        3 (<- ncu capture)
    dd_markw  <<<640, 256>>>(captions, Wf, Wb);
    dd_compact<<<NBLK, 256>>>();

    dim3 gg(4, (NTOK + 127) / 128);
    gemm_tc<<<gg, 256, G_SMEM>>>(E);

    dim3 gl(BATCH / 64, 2);
    lstm_fused<<<gl, 256, L_SMEM>>>(captions, h0f, c0f, h0b, c0b,
                                    Uf, bf, Ub, bb, out);
}

// round 13
// speedup vs baseline: 1.2118x; 1.2118x over previous
#include <cuda_runtime.h>
#include <cuda_fp16.h>
#include <cstdint>

#define NTOK  50257
#define NIN   300
#define KPAD  320
#define TT    18
#define BATCH 4096
#define NCAP  (BATCH * TT)
#define NBLK  197              // ceil(NTOK/256)

typedef unsigned long long ull;

// ---------------- device scratch (no allocations allowed) ----------------
__device__ __half  g_EW [(size_t)NTOK * 512];   // fp16! [slot][dir*256 + gate*64 + kk]
__device__ __half  g_Wh [(size_t)512 * KPAD];   // [n][k], fp16
__device__ int g_flag[NTOK];    // generation-stamped presence flags
__device__ int g_list[NTOK];
__device__ int g_slot[NTOK];
__device__ int g_count;
__device__ int g_gen;           // increments once per kernel_launch (in lstm)

// ---------------- activation helpers ----------------
__device__ __forceinline__ float tanha(float x){
    float r; asm("tanh.approx.f32 %0, %1;" : "=f"(r) : "f"(x)); return r;
}
__device__ __forceinline__ float sigmt(float x){   // 0.5 + 0.5*tanh(x/2)
    return fmaf(tanha(x * 0.5f), 0.5f, 0.5f);
}

// ---------------- mma.sync helpers ----------------
__device__ __forceinline__ uint32_t smem_u32(const void* p){
    uint32_t a; asm("{ .reg .u64 t; cvta.to.shared.u64 t, %1; cvt.u32.u64 %0, t; }" : "=r"(a) : "l"(p));
    return a;
}
__device__ __forceinline__ void ldm4(uint32_t (&r)[4], uint32_t addr){
    asm volatile("ldmatrix.sync.aligned.m8n8.x4.shared.b16 {%0,%1,%2,%3}, [%4];"
        : "=r"(r[0]), "=r"(r[1]), "=r"(r[2]), "=r"(r[3]) : "r"(addr));
}
__device__ __forceinline__ void ldm2(uint32_t& r0, uint32_t& r1, uint32_t addr){
    asm volatile("ldmatrix.sync.aligned.m8n8.x2.shared.b16 {%0,%1}, [%2];"
        : "=r"(r0), "=r"(r1) : "r"(addr));
}
__device__ __forceinline__ void mma16816(float (&c)[4], const uint32_t (&a)[4],
                                         uint32_t b0, uint32_t b1){
    asm volatile(
        "mma.sync.aligned.m16n8k16.row.col.f32.f16.f16.f32 "
        "{%0,%1,%2,%3}, {%4,%5,%6,%7}, {%8,%9}, {%0,%1,%2,%3};"
        : "+f"(c[0]), "+f"(c[1]), "+f"(c[2]), "+f"(c[3])
        : "r"(a[0]), "r"(a[1]), "r"(a[2]), "r"(a[3]), "r"(b0), "r"(b1));
}
__device__ __forceinline__ uint32_t pk2h(__half a, __half b){
    return (uint32_t)__half_as_ushort(a) | ((uint32_t)__half_as_ushort(b) << 16);
}

// ============================================================================
// dd_markw / dd_compact: generation-stamped token dedup (+ W fp16 convert)
// ============================================================================
__global__ void dd_markw(const int* __restrict__ cap,
                         const float* __restrict__ Wf, const float* __restrict__ Wb){
    const int idx = blockIdx.x * 256 + threadIdx.x;
    const int gen = g_gen + 1;
    if (idx < NCAP) g_flag[cap[idx]] = gen;
    if (idx == 0)   g_count = 0;
    if (idx < 512 * KPAD){
        const int n = idx / KPAD, k = idx % KPAD;
        float v = 0.f;
        if (k < NIN) v = (n < 256) ? Wf[(size_t)k * 256 + n] : Wb[(size_t)k * 256 + (n - 256)];
        g_Wh[(size_t)n * KPAD + k] = __float2half_rn(v);
    }
}
__global__ void dd_compact(){
    const int i = blockIdx.x * 256 + threadIdx.x;
    const int gen = g_gen + 1;
    if (i < NTOK && g_flag[i] == gen){
        int pos = atomicAdd(&g_count, 1);
        g_list[pos] = i;
        g_slot[i]   = pos;
    }
}

// ============================================================================
// gemm_tc (known-good): CTA 128x128, A = Ehi+Elo fp16, B = W fp16.
// Epilogue now stores fp16 (half the write traffic).
// ============================================================================
#define KT          10
#define MAT_BYTES   10240
#define STAGE_BYTES 30720
#define G_SMEM      (2 * STAGE_BYTES)

__global__ void __launch_bounds__(256, 2) gemm_tc(const float* __restrict__ E)
{
    const int cnt = g_count;
    const int m0  = blockIdx.y * 128;
    if (m0 >= cnt) return;

    extern __shared__ char sm[];
    const uint32_t smb = smem_u32(sm);
    const int tid = threadIdx.x, lane = tid & 31, wid = tid >> 5;
    const int slab = blockIdx.x;
    const int warp_m = (wid >> 2) * 64;
    const int warp_n = (wid & 3) * 32;

    const int erow = tid >> 1, eh = tid & 1;
    const int wn   = tid >> 1, wc = tid & 1;
    const int gm   = m0 + erow;
    const int tokE = (gm < cnt) ? g_list[gm] : g_list[0];
    const float* Ebase = E + (size_t)tokE * NIN;
    const __half* WHb  = g_Wh + (size_t)(slab * 128 + wn) * KPAD;

    float4 eR[4]; uint4 wR[2];

    auto LDGT = [&](int kt){
        const int k0 = kt * 32;
        #pragma unroll
        for (int j = 0; j < 4; j++){
            const int k = k0 + eh * 16 + j * 4;
            eR[j] = (k < NIN) ? *(const float4*)(Ebase + k)
                              : make_float4(0.f, 0.f, 0.f, 0.f);
        }
        wR[0] = *(const uint4*)(WHb + k0 + wc * 16);
        wR[1] = *(const uint4*)(WHb + k0 + wc * 16 + 8);
    };
    auto STST = [&](int s){
        char* base = sm + s * STAGE_BYTES;
        #pragma unroll
        for (int j = 0; j < 4; j++){
            const float4 v = eR[j];
            const __half hx = __float2half_rn(v.x), hy = __float2half_rn(v.y);
            const __half hz = __float2half_rn(v.z), hw = __float2half_rn(v.w);
            const float lx = v.x - __half2float(hx), ly = v.y - __half2float(hy);
            const float lz = v.z - __half2float(hz), lw = v.w - __half2float(hw);
            const int koff = eh * 16 + j * 4;
            *(uint2*)(base + erow * 80 + koff * 2) =
                make_uint2(pk2h(hx, hy), pk2h(hz, hw));
            *(uint2*)(base + MAT_BYTES + erow * 80 + koff * 2) =
                make_uint2(pk2h(__float2half_rn(lx), __float2half_rn(ly)),
                           pk2h(__float2half_rn(lz), __float2half_rn(lw)));
        }
        *(uint4*)(base + 2*MAT_BYTES + wn * 80 + wc * 32)      = wR[0];
        *(uint4*)(base + 2*MAT_BYTES + wn * 80 + wc * 32 + 16) = wR[1];
    };

    float acc[4][4][4];
    #pragma unroll
    for (int a = 0; a < 4; a++)
        #pragma unroll
        for (int b = 0; b < 4; b++)
            #pragma unroll
            for (int r = 0; r < 4; r++) acc[a][b][r] = 0.f;

    const int aR = warp_m + (lane & 15);
    const int aC = (lane >> 4) * 8;
    const int bR = warp_n + (lane & 7) + ((lane >> 4) << 3);
    const int bC = ((lane >> 3) & 1) * 8;

    LDGT(0); STST(0); __syncthreads();

    #pragma unroll 1
    for (int kt = 0; kt < KT; ++kt){
        if (kt + 1 < KT) LDGT(kt + 1);
        const uint32_t sb = smb + (kt & 1) * STAGE_BYTES;

        auto DOKB = [&](int kb){
            uint32_t ah[4][4], al[4][4];
            #pragma unroll
            for (int fm = 0; fm < 4; fm++){
                ldm4(ah[fm], sb + (aR + fm*16) * 80 + (aC + kb) * 2);
                ldm4(al[fm], sb + MAT_BYTES + (aR + fm*16) * 80 + (aC + kb) * 2);
            }
            uint32_t bh[4][2];
            #pragma unroll
            for (int g = 0; g < 2; g++){
                uint32_t t[4];
                ldm4(t, sb + 2*MAT_BYTES + (bR + g*16) * 80 + (bC + kb) * 2);
                bh[2*g][0] = t[0]; bh[2*g][1] = t[1]; bh[2*g+1][0] = t[2]; bh[2*g+1][1] = t[3];
            }
            #pragma unroll
            for (int fm = 0; fm < 4; fm++)
                #pragma unroll
                for (int fn = 0; fn < 4; fn++){
                    mma16816(acc[fm][fn], ah[fm], bh[fn][0], bh[fn][1]);
                    mma16816(acc[fm][fn], al[fm], bh[fn][0], bh[fn][1]);
                }
        };
        DOKB(0);
        if (kt < KT - 1) DOKB(16);

        if (kt + 1 < KT) STST((kt + 1) & 1);
        __syncthreads();
    }

    const int rBase = m0 + warp_m + (lane >> 2);
    const int cBase = slab * 128 + warp_n + (lane & 3) * 2;
    #pragma unroll
    for (int fm = 0; fm < 4; fm++)
        #pragma unroll
        for (int fn = 0; fn < 4; fn++){
            const int r0 = rBase + fm * 16;
            const int cc = cBase + fn * 8;
            if (r0 < cnt)
                *(__half2*)&g_EW[(size_t)r0 * 512 + cc] =
                    __floats2half2_rn(acc[fm][fn][0], acc[fm][fn][1]);
            if (r0 + 8 < cnt)
                *(__half2*)&g_EW[(size_t)(r0 + 8) * 512 + cc] =
                    __floats2half2_rn(acc[fm][fn][2], acc[fm][fn][3]);
        }
}

// ============================================================================
// LSTM v11 — exact R9 structure (best: 129.7us), EW gather now fp16
// (half the per-step DRAM traffic; 40MB dedup'd EW fits L2).
// ============================================================================
#define HP      72
#define UTH_OFF 0
#define UTL_OFF 36864
#define H_OFF   73728
#define H_PL    (64 * HP * 2)
#define TOK_OFF (H_OFF + 4 * H_PL)
#define L_SMEM  (TOK_OFF + 64 * TT * 4)

__global__ void __launch_bounds__(256, 1) lstm_fused(
    const int*   __restrict__ cap,
    const float* __restrict__ h0f, const float* __restrict__ c0f,
    const float* __restrict__ h0b, const float* __restrict__ c0b,
    const float* __restrict__ Uf,  const float* __restrict__ bf,
    const float* __restrict__ Ub,  const float* __restrict__ bb,
    float* __restrict__ out)
{
    extern __shared__ char sm[];
    const uint32_t smb = smem_u32(sm);
    __half* UTH = (__half*)(sm + UTH_OFF);
    __half* UTL = (__half*)(sm + UTL_OFF);
    int (*toks)[TT] = (int(*)[TT])(sm + TOK_OFF);

    const int dir = blockIdx.y;
    const float* U  = dir ? Ub  : Uf;
    const float* bv = dir ? bb  : bf;
    const float* h0 = dir ? h0b : h0f;
    const float* c0 = dir ? c0b : c0f;
    const int b0   = blockIdx.x * 64;
    const int tid  = threadIdx.x;
    const int lane = tid & 31;
    const int w    = tid >> 5;

    for (int idx = tid; idx < 64 * 256; idx += 256){
        const int kk = idx >> 8, n = idx & 255;
        const float v = U[kk * 256 + n];
        const __half hi = __float2half_rn(v);
        UTH[n * HP + kk] = hi;
        UTL[n * HP + kk] = __float2half_rn(v - __half2float(hi));
    }
    for (int idx = tid; idx < 64 * TT; idx += 256)
        toks[idx / TT][idx % TT] = g_slot[cap[b0 * TT + idx]];
    {
        __half* Hhi = (__half*)(sm + H_OFF);
        __half* Hlo = (__half*)(sm + H_OFF + H_PL);
        for (int idx = tid; idx < 64 * 64; idx += 256){
            const int r = idx >> 6, kk = idx & 63;
            const float v = h0[(size_t)(b0 + r) * 64 + kk];
            const __half hi = __float2half_rn(v);
            Hhi[r * HP + kk] = hi;
            Hlo[r * HP + kk] = __float2half_rn(v - __half2float(hi));
        }
    }

    const int kkg = w * 8 + (lane & 3) * 2;
    float c[16];
    #pragma unroll
    for (int m = 0; m < 4; m++)
        #pragma unroll
        for (int r = 0; r < 2; r++)
            #pragma unroll
            for (int j = 0; j < 2; j++){
                const int row = m * 16 + (lane >> 2) + r * 8;
                c[m*4 + r*2 + j] = c0[(size_t)(b0 + row) * 64 + kkg + j];
            }
    float bias[4][2];
    #pragma unroll
    for (int g = 0; g < 4; g++){
        bias[g][0] = bv[g * 64 + kkg];
        bias[g][1] = bv[g * 64 + kkg + 1];
    }
    __syncthreads();

    uint32_t uh[4][4][2], ul[4][4][2];
    #pragma unroll
    for (int g = 0; g < 4; g++)
        #pragma unroll
        for (int kt = 0; kt < 4; kt++){
            const uint32_t off =
                (uint32_t)((g*64 + w*8 + (lane & 7)) * HP + kt*16 + ((lane >> 3) & 1) * 8) * 2;
            ldm2(uh[g][kt][0], uh[g][kt][1], smb + UTH_OFF + off);
            ldm2(ul[g][kt][0], ul[g][kt][1], smb + UTL_OFF + off);
        }

    const size_t sent_off = (size_t)BATCH * 128 * TT;
    const int aR = lane & 15;
    const int aC = (lane >> 4) * 8;
    float hprev[16];

    for (int s = 0; s < TT; ++s){
        __syncthreads();
        const int t = dir ? (TT - 1 - s) : s;
        const int p = s & 1;
        const uint32_t hHi = smb + H_OFF + (p*2 + 0) * H_PL;
        const uint32_t hLo = smb + H_OFF + (p*2 + 1) * H_PL;

        // acc init = fp16 EW gather + bias (LDGs batch at step start)
        float acc[4][4][4];
        #pragma unroll
        for (int m = 0; m < 4; m++){
            #pragma unroll
            for (int r = 0; r < 2; r++){
                const int row  = m * 16 + (lane >> 2) + r * 8;
                const int slot = toks[row][t];
                const __half* ew = g_EW + (size_t)slot * 512 + dir * 256 + kkg;
                #pragma unroll
                for (int g = 0; g < 4; g++){
                    const __half2 e = *(const __half2*)(ew + g * 64);
                    acc[m][g][r*2 + 0] = __low2float(e)  + bias[g][0];
                    acc[m][g][r*2 + 1] = __high2float(e) + bias[g][1];
                }
            }
        }

        // z += h @ U  (3-term tensor-core)
        #pragma unroll
        for (int kt = 0; kt < 4; kt++){
            uint32_t ahi[4][4], alo[4][4];
            #pragma unroll
            for (int m = 0; m < 4; m++){
                const uint32_t off = (uint32_t)((aR + m*16) * HP + aC + kt*16) * 2;
                ldm4(ahi[m], hHi + off);
                ldm4(alo[m], hLo + off);
            }
            #pragma unroll
            for (int m = 0; m < 4; m++)
                #pragma unroll
                for (int g = 0; g < 4; g++){
                    mma16816(acc[m][g], ahi[m], uh[g][kt][0], uh[g][kt][1]);
                    mma16816(acc[m][g], alo[m], uh[g][kt][0], uh[g][kt][1]);
                    mma16816(acc[m][g], ahi[m], ul[g][kt][0], ul[g][kt][1]);
                }
        }

        // epilogue: activations, c update, h stores
        const uint32_t nHi = smb + H_OFF + ((p^1)*2 + 0) * H_PL;
        const uint32_t nLo = smb + H_OFF + ((p^1)*2 + 1) * H_PL;
        #pragma unroll
        for (int m = 0; m < 4; m++){
            #pragma unroll
            for (int r = 0; r < 2; r++){
                const int row = m * 16 + (lane >> 2) + r * 8;
                float hv[2];
                #pragma unroll
                for (int j = 0; j < 2; j++){
                    const int e = r*2 + j;
                    const float ig = sigmt(acc[m][0][e]);
                    const float fg = sigmt(acc[m][1][e]);
                    const float gg = tanha(acc[m][2][e]);
                    const float og = sigmt(acc[m][3][e]);
                    const float cn = fg * c[m*4 + e] + ig * gg;
                    c[m*4 + e] = cn;
                    hv[j] = og * tanha(cn);

                    if (s == TT - 1)
                        out[sent_off + (size_t)(b0 + row) * 128 + dir*64 + kkg + j] = hv[j];

                    if (s & 1){
                        const int tlo = dir ? t : t - 1;
                        const float2 v = dir ? make_float2(hv[j], hprev[m*4 + e])
                                             : make_float2(hprev[m*4 + e], hv[j]);
                        *(float2*)&out[(size_t)(b0 + row) * (128*TT)
                                       + (dir*64 + kkg + j) * TT + tlo] = v;
                    } else {
                        hprev[m*4 + e] = hv[j];
                    }
                }
                const __half h0h = __float2half_rn(hv[0]);
                const __half h1h = __float2half_rn(hv[1]);
                const __half l0h = __float2half_rn(hv[0] - __half2float(h0h));
                const __half l1h = __float2half_rn(hv[1] - __half2float(h1h));
                const uint32_t soff = (uint32_t)(row * HP + kkg) * 2;
                *(uint32_t*)(sm + (nHi - smb) + soff) = pk2h(h0h, h1h);
                *(uint32_t*)(sm + (nLo - smb) + soff) = pk2h(l0h, l1h);
            }
        }
    }

    if (tid == 0 && blockIdx.x == 0 && blockIdx.y == 0)
        g_gen += 1;
}

// ============================================================================
extern "C" void kernel_launch(void* const* d_in, const int* in_sizes, int n_in,
                              void* d_out, int out_size)
{
    const int*   captions = (const int*)  d_in[0];
    const float* h0f = (const float*)d_in[2];
    const float* c0f = (const float*)d_in[3];
    const float* h0b = (const float*)d_in[4];
    const float* c0b = (const float*)d_in[5];
    const float* E   = (const float*)d_in[6];
    const float* Wf  = (const float*)d_in[7];
    const float* Uf  = (const float*)d_in[8];
    const float* bf  = (const float*)d_in[9];
    const float* Wb  = (const float*)d_in[10];
    const float* Ub  = (const float*)d_in[11];
    const float* bb  = (const float*)d_in[12];
    float* out = (float*)d_out;

    cudaFuncSetAttribute(gemm_tc,    cudaFuncAttributeMaxDynamicSharedMemorySize, G_SMEM);
    cudaFuncSetAttribute(lstm_fused, cudaFuncAttributeMaxDynamicSharedMemorySize, L_SMEM);

    // launch index:   0          1           2        3 (<- ncu capture)
    dd_markw  <<<640, 256>>>(captions, Wf, Wb);
    dd_compact<<<NBLK, 256>>>();

    dim3 gg(4, (NTOK + 127) / 128);
    gemm_tc<<<gg, 256, G_SMEM>>>(E);

    dim3 gl(BATCH / 64, 2);
    lstm_fused<<<gl, 256, L_SMEM>>>(captions, h0f, c0f, h0b, c0b,
                                    Uf, bf, Ub, bb, out);
}

// round 14
// speedup vs baseline: 1.3561x; 1.1191x over previous
#include <cuda_runtime.h>
#include <cuda_fp16.h>
#include <cstdint>

#define NTOK  50257
#define NIN   300
#define KPAD  320
#define TT    18
#define BATCH 4096
#define NCAP  (BATCH * TT)
#define NBLK  197              // ceil(NTOK/256)

typedef unsigned long long ull;

// ---------------- device scratch (no allocations allowed) ----------------
__device__ __half  g_EW [(size_t)NTOK * 512];   // fp16 [slot][dir*256 + gate*64 + kk]
__device__ __half  g_Wh [(size_t)512 * KPAD];   // [n][k], fp16
__device__ int g_flag[NTOK];    // generation-stamped presence flags
__device__ int g_list[NTOK];
__device__ int g_slot[NTOK];
__device__ int g_count;
__device__ int g_gen;           // increments once per kernel_launch (in lstm)

// ---------------- activation helpers ----------------
__device__ __forceinline__ float tanha(float x){
    float r; asm("tanh.approx.f32 %0, %1;" : "=f"(r) : "f"(x)); return r;
}
__device__ __forceinline__ float sigmt(float x){   // 0.5 + 0.5*tanh(x/2)
    return fmaf(tanha(x * 0.5f), 0.5f, 0.5f);
}

// ---------------- mma.sync helpers ----------------
__device__ __forceinline__ uint32_t smem_u32(const void* p){
    uint32_t a; asm("{ .reg .u64 t; cvta.to.shared.u64 t, %1; cvt.u32.u64 %0, t; }" : "=r"(a) : "l"(p));
    return a;
}
__device__ __forceinline__ void ldm4(uint32_t (&r)[4], uint32_t addr){
    asm volatile("ldmatrix.sync.aligned.m8n8.x4.shared.b16 {%0,%1,%2,%3}, [%4];"
        : "=r"(r[0]), "=r"(r[1]), "=r"(r[2]), "=r"(r[3]) : "r"(addr));
}
__device__ __forceinline__ void ldm2(uint32_t& r0, uint32_t& r1, uint32_t addr){
    asm volatile("ldmatrix.sync.aligned.m8n8.x2.shared.b16 {%0,%1}, [%2];"
        : "=r"(r0), "=r"(r1) : "r"(addr));
}
__device__ __forceinline__ void mma16816(float (&c)[4], const uint32_t (&a)[4],
                                         uint32_t b0, uint32_t b1){
    asm volatile(
        "mma.sync.aligned.m16n8k16.row.col.f32.f16.f16.f32 "
        "{%0,%1,%2,%3}, {%4,%5,%6,%7}, {%8,%9}, {%0,%1,%2,%3};"
        : "+f"(c[0]), "+f"(c[1]), "+f"(c[2]), "+f"(c[3])
        : "r"(a[0]), "r"(a[1]), "r"(a[2]), "r"(a[3]), "r"(b0), "r"(b1));
}
__device__ __forceinline__ uint32_t pk2h(__half a, __half b){
    return (uint32_t)__half_as_ushort(a) | ((uint32_t)__half_as_ushort(b) << 16);
}

// ============================================================================
// dd_markw / dd_compact: generation-stamped token dedup (+ W fp16 convert)
// ============================================================================
__global__ void dd_markw(const int* __restrict__ cap,
                         const float* __restrict__ Wf, const float* __restrict__ Wb){
    const int idx = blockIdx.x * 256 + threadIdx.x;
    const int gen = g_gen + 1;
    if (idx < NCAP) g_flag[cap[idx]] = gen;
    if (idx == 0)   g_count = 0;
    if (idx < 512 * KPAD){
        const int n = idx / KPAD, k = idx % KPAD;
        float v = 0.f;
        if (k < NIN) v = (n < 256) ? Wf[(size_t)k * 256 + n] : Wb[(size_t)k * 256 + (n - 256)];
        g_Wh[(size_t)n * KPAD + k] = __float2half_rn(v);
    }
}
__global__ void dd_compact(){
    const int i = blockIdx.x * 256 + threadIdx.x;
    const int gen = g_gen + 1;
    if (i < NTOK && g_flag[i] == gen){
        int pos = atomicAdd(&g_count, 1);
        g_list[pos] = i;
        g_slot[i]   = pos;
    }
}

// ============================================================================
// gemm_tc v5: single-term fp16 GEMM (A = E fp16, B = W fp16).
// CTA 128x128, warp 64x32. smem/stage: A 10240 | B 10240 = 20480, x2.
// ============================================================================
#define KT          10
#define MAT_BYTES   10240
#define STAGE_BYTES 20480
#define G_SMEM      (2 * STAGE_BYTES)

__global__ void __launch_bounds__(256, 2) gemm_tc(const float* __restrict__ E)
{
    const int cnt = g_count;
    const int m0  = blockIdx.y * 128;
    if (m0 >= cnt) return;

    extern __shared__ char sm[];
    const uint32_t smb = smem_u32(sm);
    const int tid = threadIdx.x, lane = tid & 31, wid = tid >> 5;
    const int slab = blockIdx.x;
    const int warp_m = (wid >> 2) * 64;
    const int warp_n = (wid & 3) * 32;

    const int erow = tid >> 1, eh = tid & 1;
    const int wn   = tid >> 1, wc = tid & 1;
    const int gm   = m0 + erow;
    const int tokE = (gm < cnt) ? g_list[gm] : g_list[0];
    const float* Ebase = E + (size_t)tokE * NIN;
    const __half* WHb  = g_Wh + (size_t)(slab * 128 + wn) * KPAD;

    float4 eR[4]; uint4 wR[2];

    auto LDGT = [&](int kt){
        const int k0 = kt * 32;
        #pragma unroll
        for (int j = 0; j < 4; j++){
            const int k = k0 + eh * 16 + j * 4;
            eR[j] = (k < NIN) ? *(const float4*)(Ebase + k)
                              : make_float4(0.f, 0.f, 0.f, 0.f);
        }
        wR[0] = *(const uint4*)(WHb + k0 + wc * 16);
        wR[1] = *(const uint4*)(WHb + k0 + wc * 16 + 8);
    };
    auto STST = [&](int s){
        char* base = sm + s * STAGE_BYTES;
        #pragma unroll
        for (int j = 0; j < 4; j++){
            const float4 v = eR[j];
            const int koff = eh * 16 + j * 4;
            *(uint2*)(base + erow * 80 + koff * 2) =
                make_uint2(pk2h(__float2half_rn(v.x), __float2half_rn(v.y)),
                           pk2h(__float2half_rn(v.z), __float2half_rn(v.w)));
        }
        *(uint4*)(base + MAT_BYTES + wn * 80 + wc * 32)      = wR[0];
        *(uint4*)(base + MAT_BYTES + wn * 80 + wc * 32 + 16) = wR[1];
    };

    float acc[4][4][4];
    #pragma unroll
    for (int a = 0; a < 4; a++)
        #pragma unroll
        for (int b = 0; b < 4; b++)
            #pragma unroll
            for (int r = 0; r < 4; r++) acc[a][b][r] = 0.f;

    const int aR = warp_m + (lane & 15);
    const int aC = (lane >> 4) * 8;
    const int bR = warp_n + (lane & 7) + ((lane >> 4) << 3);
    const int bC = ((lane >> 3) & 1) * 8;

    LDGT(0); STST(0); __syncthreads();

    #pragma unroll 1
    for (int kt = 0; kt < KT; ++kt){
        if (kt + 1 < KT) LDGT(kt + 1);
        const uint32_t sb = smb + (kt & 1) * STAGE_BYTES;

        auto DOKB = [&](int kb){
            uint32_t ah[4][4];
            #pragma unroll
            for (int fm = 0; fm < 4; fm++)
                ldm4(ah[fm], sb + (aR + fm*16) * 80 + (aC + kb) * 2);
            uint32_t bh[4][2];
            #pragma unroll
            for (int g = 0; g < 2; g++){
                uint32_t t[4];
                ldm4(t, sb + MAT_BYTES + (bR + g*16) * 80 + (bC + kb) * 2);
                bh[2*g][0] = t[0]; bh[2*g][1] = t[1]; bh[2*g+1][0] = t[2]; bh[2*g+1][1] = t[3];
            }
            #pragma unroll
            for (int fm = 0; fm < 4; fm++)
                #pragma unroll
                for (int fn = 0; fn < 4; fn++)
                    mma16816(acc[fm][fn], ah[fm], bh[fn][0], bh[fn][1]);
        };
        DOKB(0);
        if (kt < KT - 1) DOKB(16);

        if (kt + 1 < KT) STST((kt + 1) & 1);
        __syncthreads();
    }

    const int rBase = m0 + warp_m + (lane >> 2);
    const int cBase = slab * 128 + warp_n + (lane & 3) * 2;
    #pragma unroll
    for (int fm = 0; fm < 4; fm++)
        #pragma unroll
        for (int fn = 0; fn < 4; fn++){
            const int r0 = rBase + fm * 16;
            const int cc = cBase + fn * 8;
            if (r0 < cnt)
                *(__half2*)&g_EW[(size_t)r0 * 512 + cc] =
                    __floats2half2_rn(acc[fm][fn][0], acc[fm][fn][1]);
            if (r0 + 8 < cnt)
                *(__half2*)&g_EW[(size_t)(r0 + 8) * 512 + cc] =
                    __floats2half2_rn(acc[fm][fn][2], acc[fm][fn][3]);
        }
}

// ============================================================================
// LSTM v11 (unchanged from R13 best: 121.4us) — tensor-core recurrence,
// 3-term h/U split, fp16 EW gather.
// ============================================================================
#define HP      72
#define UTH_OFF 0
#define UTL_OFF 36864
#define H_OFF   73728
#define H_PL    (64 * HP * 2)
#define TOK_OFF (H_OFF + 4 * H_PL)
#define L_SMEM  (TOK_OFF + 64 * TT * 4)

__global__ void __launch_bounds__(256, 1) lstm_fused(
    const int*   __restrict__ cap,
    const float* __restrict__ h0f, const float* __restrict__ c0f,
    const float* __restrict__ h0b, const float* __restrict__ c0b,
    const float* __restrict__ Uf,  const float* __restrict__ bf,
    const float* __restrict__ Ub,  const float* __restrict__ bb,
    float* __restrict__ out)
{
    extern __shared__ char sm[];
    const uint32_t smb = smem_u32(sm);
    __half* UTH = (__half*)(sm + UTH_OFF);
    __half* UTL = (__half*)(sm + UTL_OFF);
    int (*toks)[TT] = (int(*)[TT])(sm + TOK_OFF);

    const int dir = blockIdx.y;
    const float* U  = dir ? Ub  : Uf;
    const float* bv = dir ? bb  : bf;
    const float* h0 = dir ? h0b : h0f;
    const float* c0 = dir ? c0b : c0f;
    const int b0   = blockIdx.x * 64;
    const int tid  = threadIdx.x;
    const int lane = tid & 31;
    const int w    = tid >> 5;

    for (int idx = tid; idx < 64 * 256; idx += 256){
        const int kk = idx >> 8, n = idx & 255;
        const float v = U[kk * 256 + n];
        const __half hi = __float2half_rn(v);
        UTH[n * HP + kk] = hi;
        UTL[n * HP + kk] = __float2half_rn(v - __half2float(hi));
    }
    for (int idx = tid; idx < 64 * TT; idx += 256)
        toks[idx / TT][idx % TT] = g_slot[cap[b0 * TT + idx]];
    {
        __half* Hhi = (__half*)(sm + H_OFF);
        __half* Hlo = (__half*)(sm + H_OFF + H_PL);
        for (int idx = tid; idx < 64 * 64; idx += 256){
            const int r = idx >> 6, kk = idx & 63;
            const float v = h0[(size_t)(b0 + r) * 64 + kk];
            const __half hi = __float2half_rn(v);
            Hhi[r * HP + kk] = hi;
            Hlo[r * HP + kk] = __float2half_rn(v - __half2float(hi));
        }
    }

    const int kkg = w * 8 + (lane & 3) * 2;
    float c[16];
    #pragma unroll
    for (int m = 0; m < 4; m++)
        #pragma unroll
        for (int r = 0; r < 2; r++)
            #pragma unroll
            for (int j = 0; j < 2; j++){
                const int row = m * 16 + (lane >> 2) + r * 8;
                c[m*4 + r*2 + j] = c0[(size_t)(b0 + row) * 64 + kkg + j];
            }
    float bias[4][2];
    #pragma unroll
    for (int g = 0; g < 4; g++){
        bias[g][0] = bv[g * 64 + kkg];
        bias[g][1] = bv[g * 64 + kkg + 1];
    }
    __syncthreads();

    uint32_t uh[4][4][2], ul[4][4][2];
    #pragma unroll
    for (int g = 0; g < 4; g++)
        #pragma unroll
        for (int kt = 0; kt < 4; kt++){
            const uint32_t off =
                (uint32_t)((g*64 + w*8 + (lane & 7)) * HP + kt*16 + ((lane >> 3) & 1) * 8) * 2;
            ldm2(uh[g][kt][0], uh[g][kt][1], smb + UTH_OFF + off);
            ldm2(ul[g][kt][0], ul[g][kt][1], smb + UTL_OFF + off);
        }

    const size_t sent_off = (size_t)BATCH * 128 * TT;
    const int aR = lane & 15;
    const int aC = (lane >> 4) * 8;
    float hprev[16];

    for (int s = 0; s < TT; ++s){
        __syncthreads();
        const int t = dir ? (TT - 1 - s) : s;
        const int p = s & 1;
        const uint32_t hHi = smb + H_OFF + (p*2 + 0) * H_PL;
        const uint32_t hLo = smb + H_OFF + (p*2 + 1) * H_PL;

        float acc[4][4][4];
        #pragma unroll
        for (int m = 0; m < 4; m++){
            #pragma unroll
            for (int r = 0; r < 2; r++){
                const int row  = m * 16 + (lane >> 2) + r * 8;
                const int slot = toks[row][t];
                const __half* ew = g_EW + (size_t)slot * 512 + dir * 256 + kkg;
                #pragma unroll
                for (int g = 0; g < 4; g++){
                    const __half2 e = *(const __half2*)(ew + g * 64);
                    acc[m][g][r*2 + 0] = __low2float(e)  + bias[g][0];
                    acc[m][g][r*2 + 1] = __high2float(e) + bias[g][1];
                }
            }
        }

        #pragma unroll
        for (int kt = 0; kt < 4; kt++){
            uint32_t ahi[4][4], alo[4][4];
            #pragma unroll
            for (int m = 0; m < 4; m++){
                const uint32_t off = (uint32_t)((aR + m*16) * HP + aC + kt*16) * 2;
                ldm4(ahi[m], hHi + off);
                ldm4(alo[m], hLo + off);
            }
            #pragma unroll
            for (int m = 0; m < 4; m++)
                #pragma unroll
                for (int g = 0; g < 4; g++){
                    mma16816(acc[m][g], ahi[m], uh[g][kt][0], uh[g][kt][1]);
                    mma16816(acc[m][g], alo[m], uh[g][kt][0], uh[g][kt][1]);
                    mma16816(acc[m][g], ahi[m], ul[g][kt][0], ul[g][kt][1]);
                }
        }

        const uint32_t nHi = smb + H_OFF + ((p^1)*2 + 0) * H_PL;
        const uint32_t nLo = smb + H_OFF + ((p^1)*2 + 1) * H_PL;
        #pragma unroll
        for (int m = 0; m < 4; m++){
            #pragma unroll
            for (int r = 0; r < 2; r++){
                const int row = m * 16 + (lane >> 2) + r * 8;
                float hv[2];
                #pragma unroll
                for (int j = 0; j < 2; j++){
                    const int e = r*2 + j;
                    const float ig = sigmt(acc[m][0][e]);
                    const float fg = sigmt(acc[m][1][e]);
                    const float gg = tanha(acc[m][2][e]);
                    const float og = sigmt(acc[m][3][e]);
                    const float cn = fg * c[m*4 + e] + ig * gg;
                    c[m*4 + e] = cn;
                    hv[j] = og * tanha(cn);

                    if (s == TT - 1)
                        out[sent_off + (size_t)(b0 + row) * 128 + dir*64 + kkg + j] = hv[j];

                    if (s & 1){
                        const int tlo = dir ? t : t - 1;
                        const float2 v = dir ? make_float2(hv[j], hprev[m*4 + e])
                                             : make_float2(hprev[m*4 + e], hv[j]);
                        *(float2*)&out[(size_t)(b0 + row) * (128*TT)
                                       + (dir*64 + kkg + j) * TT + tlo] = v;
                    } else {
                        hprev[m*4 + e] = hv[j];
                    }
                }
                const __half h0h = __float2half_rn(hv[0]);
                const __half h1h = __float2half_rn(hv[1]);
                const __half l0h = __float2half_rn(hv[0] - __half2float(h0h));
                const __half l1h = __float2half_rn(hv[1] - __half2float(h1h));
                const uint32_t soff = (uint32_t)(row * HP + kkg) * 2;
                *(uint32_t*)(sm + (nHi - smb) + soff) = pk2h(h0h, h1h);
                *(uint32_t*)(sm + (nLo - smb) + soff) = pk2h(l0h, l1h);
            }
        }
    }

    if (tid == 0 && blockIdx.x == 0 && blockIdx.y == 0)
        g_gen += 1;
}

// ============================================================================
extern "C" void kernel_launch(void* const* d_in, const int* in_sizes, int n_in,
                              void* d_out, int out_size)
{
    const int*   captions = (const int*)  d_in[0];
    const float* h0f = (const float*)d_in[2];
    const float* c0f = (const float*)d_in[3];
    const float* h0b = (const float*)d_in[4];
    const float* c0b = (const float*)d_in[5];
    const float* E   = (const float*)d_in[6];
    const float* Wf  = (const float*)d_in[7];
    const float* Uf  = (const float*)d_in[8];
    const float* bf  = (const float*)d_in[9];
    const float* Wb  = (const float*)d_in[10];
    const float* Ub  = (const float*)d_in[11];
    const float* bb  = (const float*)d_in[12];
    float* out = (float*)d_out;

    cudaFuncSetAttribute(gemm_tc,    cudaFuncAttributeMaxDynamicSharedMemorySize, G_SMEM);
    cudaFuncSetAttribute(lstm_fused, cudaFuncAttributeMaxDynamicSharedMemorySize, L_SMEM);

    // launch index:   0          1           2        3 (<- ncu capture)
    dd_markw  <<<640, 256>>>(captions, Wf, Wb);
    dd_compact<<<NBLK, 256>>>();

    dim3 gg(4, (NTOK + 127) / 128);
    gemm_tc<<<gg, 256, G_SMEM>>>(E);

    dim3 gl(BATCH / 64, 2);
    lstm_fused<<<gl, 256, L_SMEM>>>(captions, h0f, c0f, h0b, c0b,
                                    Uf, bf, Ub, bb, out);
}

// round 15
// speedup vs baseline: 1.4943x; 1.1019x over previous
#include <cuda_runtime.h>
#include <cuda_fp16.h>
#include <cstdint>

#define NTOK  50257
#define NIN   300
#define KPAD  320
#define TT    18
#define BATCH 4096
#define NCAP  (BATCH * TT)
#define NBLK  197              // ceil(NTOK/256)

typedef unsigned long long ull;

// ---------------- device scratch (no allocations allowed) ----------------
__device__ __half  g_EW [(size_t)NTOK * 512];   // fp16 [slot][dir*256 + gate*64 + kk]
__device__ __half  g_Wh [(size_t)512 * KPAD];   // [n][k], fp16
__device__ int g_flag[NTOK];    // generation-stamped presence flags
__device__ int g_list[NTOK];
__device__ int g_slot[NTOK];
__device__ int g_count;
__device__ int g_gen;           // increments once per kernel_launch (in lstm)

// ---------------- activation helpers ----------------
__device__ __forceinline__ float tanha(float x){
    float r; asm("tanh.approx.f32 %0, %1;" : "=f"(r) : "f"(x)); return r;
}
__device__ __forceinline__ float sigmt(float x){   // 0.5 + 0.5*tanh(x/2)
    return fmaf(tanha(x * 0.5f), 0.5f, 0.5f);
}

// ---------------- mma.sync helpers ----------------
__device__ __forceinline__ uint32_t smem_u32(const void* p){
    uint32_t a; asm("{ .reg .u64 t; cvta.to.shared.u64 t, %1; cvt.u32.u64 %0, t; }" : "=r"(a) : "l"(p));
    return a;
}
__device__ __forceinline__ void ldm4(uint32_t (&r)[4], uint32_t addr){
    asm volatile("ldmatrix.sync.aligned.m8n8.x4.shared.b16 {%0,%1,%2,%3}, [%4];"
        : "=r"(r[0]), "=r"(r[1]), "=r"(r[2]), "=r"(r[3]) : "r"(addr));
}
__device__ __forceinline__ void ldm2(uint32_t& r0, uint32_t& r1, uint32_t addr){
    asm volatile("ldmatrix.sync.aligned.m8n8.x2.shared.b16 {%0,%1}, [%2];"
        : "=r"(r0), "=r"(r1) : "r"(addr));
}
__device__ __forceinline__ void mma16816(float (&c)[4], const uint32_t (&a)[4],
                                         uint32_t b0, uint32_t b1){
    asm volatile(
        "mma.sync.aligned.m16n8k16.row.col.f32.f16.f16.f32 "
        "{%0,%1,%2,%3}, {%4,%5,%6,%7}, {%8,%9}, {%0,%1,%2,%3};"
        : "+f"(c[0]), "+f"(c[1]), "+f"(c[2]), "+f"(c[3])
        : "r"(a[0]), "r"(a[1]), "r"(a[2]), "r"(a[3]), "r"(b0), "r"(b1));
}
__device__ __forceinline__ uint32_t pk2h(__half a, __half b){
    return (uint32_t)__half_as_ushort(a) | ((uint32_t)__half_as_ushort(b) << 16);
}

// ============================================================================
// dd_markw / dd_compact: generation-stamped token dedup (+ W fp16 convert)
// ============================================================================
__global__ void dd_markw(const int* __restrict__ cap,
                         const float* __restrict__ Wf, const float* __restrict__ Wb){
    const int idx = blockIdx.x * 256 + threadIdx.x;
    const int gen = g_gen + 1;
    if (idx < NCAP) g_flag[cap[idx]] = gen;
    if (idx == 0)   g_count = 0;
    if (idx < 512 * KPAD){
        const int n = idx / KPAD, k = idx % KPAD;
        float v = 0.f;
        if (k < NIN) v = (n < 256) ? Wf[(size_t)k * 256 + n] : Wb[(size_t)k * 256 + (n - 256)];
        g_Wh[(size_t)n * KPAD + k] = __float2half_rn(v);
    }
}
__global__ void dd_compact(){
    const int i = blockIdx.x * 256 + threadIdx.x;
    const int gen = g_gen + 1;
    if (i < NTOK && g_flag[i] == gen){
        int pos = atomicAdd(&g_count, 1);
        g_list[pos] = i;
        g_slot[i]   = pos;
    }
}

// ============================================================================
// gemm_tc v5 (R14 known-good, ~55us): single-term fp16 GEMM.
// ============================================================================
#define KT          10
#define MAT_BYTES   10240
#define STAGE_BYTES 20480
#define G_SMEM      (2 * STAGE_BYTES)

__global__ void __launch_bounds__(256, 2) gemm_tc(const float* __restrict__ E)
{
    const int cnt = g_count;
    const int m0  = blockIdx.y * 128;
    if (m0 >= cnt) return;

    extern __shared__ char sm[];
    const uint32_t smb = smem_u32(sm);
    const int tid = threadIdx.x, lane = tid & 31, wid = tid >> 5;
    const int slab = blockIdx.x;
    const int warp_m = (wid >> 2) * 64;
    const int warp_n = (wid & 3) * 32;

    const int erow = tid >> 1, eh = tid & 1;
    const int wn   = tid >> 1, wc = tid & 1;
    const int gm   = m0 + erow;
    const int tokE = (gm < cnt) ? g_list[gm] : g_list[0];
    const float* Ebase = E + (size_t)tokE * NIN;
    const __half* WHb  = g_Wh + (size_t)(slab * 128 + wn) * KPAD;

    float4 eR[4]; uint4 wR[2];

    auto LDGT = [&](int kt){
        const int k0 = kt * 32;
        #pragma unroll
        for (int j = 0; j < 4; j++){
            const int k = k0 + eh * 16 + j * 4;
            eR[j] = (k < NIN) ? *(const float4*)(Ebase + k)
                              : make_float4(0.f, 0.f, 0.f, 0.f);
        }
        wR[0] = *(const uint4*)(WHb + k0 + wc * 16);
        wR[1] = *(const uint4*)(WHb + k0 + wc * 16 + 8);
    };
    auto STST = [&](int s){
        char* base = sm + s * STAGE_BYTES;
        #pragma unroll
        for (int j = 0; j < 4; j++){
            const float4 v = eR[j];
            const int koff = eh * 16 + j * 4;
            *(uint2*)(base + erow * 80 + koff * 2) =
                make_uint2(pk2h(__float2half_rn(v.x), __float2half_rn(v.y)),
                           pk2h(__float2half_rn(v.z), __float2half_rn(v.w)));
        }
        *(uint4*)(base + MAT_BYTES + wn * 80 + wc * 32)      = wR[0];
        *(uint4*)(base + MAT_BYTES + wn * 80 + wc * 32 + 16) = wR[1];
    };

    float acc[4][4][4];
    #pragma unroll
    for (int a = 0; a < 4; a++)
        #pragma unroll
        for (int b = 0; b < 4; b++)
            #pragma unroll
            for (int r = 0; r < 4; r++) acc[a][b][r] = 0.f;

    const int aR = warp_m + (lane & 15);
    const int aC = (lane >> 4) * 8;
    const int bR = warp_n + (lane & 7) + ((lane >> 4) << 3);
    const int bC = ((lane >> 3) & 1) * 8;

    LDGT(0); STST(0); __syncthreads();

    #pragma unroll 1
    for (int kt = 0; kt < KT; ++kt){
        if (kt + 1 < KT) LDGT(kt + 1);
        const uint32_t sb = smb + (kt & 1) * STAGE_BYTES;

        auto DOKB = [&](int kb){
            uint32_t ah[4][4];
            #pragma unroll
            for (int fm = 0; fm < 4; fm++)
                ldm4(ah[fm], sb + (aR + fm*16) * 80 + (aC + kb) * 2);
            uint32_t bh[4][2];
            #pragma unroll
            for (int g = 0; g < 2; g++){
                uint32_t t[4];
                ldm4(t, sb + MAT_BYTES + (bR + g*16) * 80 + (bC + kb) * 2);
                bh[2*g][0] = t[0]; bh[2*g][1] = t[1]; bh[2*g+1][0] = t[2]; bh[2*g+1][1] = t[3];
            }
            #pragma unroll
            for (int fm = 0; fm < 4; fm++)
                #pragma unroll
                for (int fn = 0; fn < 4; fn++)
                    mma16816(acc[fm][fn], ah[fm], bh[fn][0], bh[fn][1]);
        };
        DOKB(0);
        if (kt < KT - 1) DOKB(16);

        if (kt + 1 < KT) STST((kt + 1) & 1);
        __syncthreads();
    }

    const int rBase = m0 + warp_m + (lane >> 2);
    const int cBase = slab * 128 + warp_n + (lane & 3) * 2;
    #pragma unroll
    for (int fm = 0; fm < 4; fm++)
        #pragma unroll
        for (int fn = 0; fn < 4; fn++){
            const int r0 = rBase + fm * 16;
            const int cc = cBase + fn * 8;
            if (r0 < cnt)
                *(__half2*)&g_EW[(size_t)r0 * 512 + cc] =
                    __floats2half2_rn(acc[fm][fn][0], acc[fm][fn][1]);
            if (r0 + 8 < cnt)
                *(__half2*)&g_EW[(size_t)(r0 + 8) * 512 + cc] =
                    __floats2half2_rn(acc[fm][fn][2], acc[fm][fn][3]);
        }
}

// ============================================================================
// LSTM v12 — 512 threads / 16 warps (4 per SMSP). 2-term recurrence:
// z = (h_hi + h_lo) @ U_hi. Warp (wg, wk): wg = rows [32wg,32wg+32),
// wk = kk octet for all 4 gates. Register diet: ~115 regs/thread.
// ============================================================================
#define HP      72
#define UTH_OFF 0
#define H_OFF   36864                   // U^T hi only (UTL eliminated)
#define H_PL    (64 * HP * 2)           // 9216
#define TOK_OFF (H_OFF + 4 * H_PL)      // 73728
#define L_SMEM  (TOK_OFF + 64 * TT * 4) // 78336

__global__ void __launch_bounds__(512, 1) lstm_fused(
    const int*   __restrict__ cap,
    const float* __restrict__ h0f, const float* __restrict__ c0f,
    const float* __restrict__ h0b, const float* __restrict__ c0b,
    const float* __restrict__ Uf,  const float* __restrict__ bf,
    const float* __restrict__ Ub,  const float* __restrict__ bb,
    float* __restrict__ out)
{
    extern __shared__ char sm[];
    const uint32_t smb = smem_u32(sm);
    __half* UTH = (__half*)(sm + UTH_OFF);
    int (*toks)[TT] = (int(*)[TT])(sm + TOK_OFF);

    const int dir = blockIdx.y;
    const float* U  = dir ? Ub  : Uf;
    const float* bv = dir ? bb  : bf;
    const float* h0 = dir ? h0b : h0f;
    const float* c0 = dir ? c0b : c0f;
    const int b0   = blockIdx.x * 64;
    const int tid  = threadIdx.x;
    const int lane = tid & 31;
    const int w    = tid >> 5;           // 0..15
    const int wk   = w & 7;              // kk octet
    const int wg   = w >> 3;             // row half: 0 -> rows 0..31, 1 -> 32..63
    const int rbase = wg * 32;

    // ---- prologue: U^T hi, tokens, h0 hi/lo planes ----
    for (int idx = tid; idx < 64 * 256; idx += 512){
        const int kk = idx >> 8, n = idx & 255;
        UTH[n * HP + kk] = __float2half_rn(U[kk * 256 + n]);
    }
    for (int idx = tid; idx < 64 * TT; idx += 512)
        toks[idx / TT][idx % TT] = g_slot[cap[b0 * TT + idx]];
    {
        __half* Hhi = (__half*)(sm + H_OFF);
        __half* Hlo = (__half*)(sm + H_OFF + H_PL);
        for (int idx = tid; idx < 64 * 64; idx += 512){
            const int r = idx >> 6, kk = idx & 63;
            const float v = h0[(size_t)(b0 + r) * 64 + kk];
            const __half hi = __float2half_rn(v);
            Hhi[r * HP + kk] = hi;
            Hlo[r * HP + kk] = __float2half_rn(v - __half2float(hi));
        }
    }

    const int kkg = wk * 8 + (lane & 3) * 2;
    float c[8];
    #pragma unroll
    for (int m = 0; m < 2; m++)
        #pragma unroll
        for (int r = 0; r < 2; r++)
            #pragma unroll
            for (int j = 0; j < 2; j++){
                const int row = rbase + m * 16 + (lane >> 2) + r * 8;
                c[m*4 + r*2 + j] = c0[(size_t)(b0 + row) * 64 + kkg + j];
            }
    float bias[4][2];
    #pragma unroll
    for (int g = 0; g < 4; g++){
        bias[g][0] = bv[g * 64 + kkg];
        bias[g][1] = bv[g * 64 + kkg + 1];
    }
    __syncthreads();

    // ---- U fragments (hi only): register-resident ----
    uint32_t uh[4][4][2];
    #pragma unroll
    for (int g = 0; g < 4; g++)
        #pragma unroll
        for (int kt = 0; kt < 4; kt++){
            const uint32_t off =
                (uint32_t)((g*64 + wk*8 + (lane & 7)) * HP + kt*16 + ((lane >> 3) & 1) * 8) * 2;
            ldm2(uh[g][kt][0], uh[g][kt][1], smb + UTH_OFF + off);
        }

    const size_t sent_off = (size_t)BATCH * 128 * TT;
    const int aR = rbase + (lane & 15);
    const int aC = (lane >> 4) * 8;
    float hprev[8];

    for (int s = 0; s < TT; ++s){
        __syncthreads();
        const int t = dir ? (TT - 1 - s) : s;
        const int p = s & 1;
        const uint32_t hHi = smb + H_OFF + (p*2 + 0) * H_PL;
        const uint32_t hLo = smb + H_OFF + (p*2 + 1) * H_PL;

        // acc init = fp16 EW gather + bias
        float acc[2][4][4];
        #pragma unroll
        for (int m = 0; m < 2; m++){
            #pragma unroll
            for (int r = 0; r < 2; r++){
                const int row  = rbase + m * 16 + (lane >> 2) + r * 8;
                const int slot = toks[row][t];
                const __half* ew = g_EW + (size_t)slot * 512 + dir * 256 + kkg;
                #pragma unroll
                for (int g = 0; g < 4; g++){
                    const __half2 e = *(const __half2*)(ew + g * 64);
                    acc[m][g][r*2 + 0] = __low2float(e)  + bias[g][0];
                    acc[m][g][r*2 + 1] = __high2float(e) + bias[g][1];
                }
            }
        }

        // z += (h_hi + h_lo) @ U_hi
        #pragma unroll
        for (int kt = 0; kt < 4; kt++){
            uint32_t ahi[2][4], alo[2][4];
            #pragma unroll
            for (int m = 0; m < 2; m++){
                const uint32_t off = (uint32_t)((aR + m*16) * HP + aC + kt*16) * 2;
                ldm4(ahi[m], hHi + off);
                ldm4(alo[m], hLo + off);
            }
            #pragma unroll
            for (int m = 0; m < 2; m++)
                #pragma unroll
                for (int g = 0; g < 4; g++){
                    mma16816(acc[m][g], ahi[m], uh[g][kt][0], uh[g][kt][1]);
                    mma16816(acc[m][g], alo[m], uh[g][kt][0], uh[g][kt][1]);
                }
        }

        // epilogue
        const uint32_t nHi = smb + H_OFF + ((p^1)*2 + 0) * H_PL;
        const uint32_t nLo = smb + H_OFF + ((p^1)*2 + 1) * H_PL;
        #pragma unroll
        for (int m = 0; m < 2; m++){
            #pragma unroll
            for (int r = 0; r < 2; r++){
                const int row = rbase + m * 16 + (lane >> 2) + r * 8;
                float hv[2];
                #pragma unroll
                for (int j = 0; j < 2; j++){
                    const int e = r*2 + j;
                    const float ig = sigmt(acc[m][0][e]);
                    const float fg = sigmt(acc[m][1][e]);
                    const float gg = tanha(acc[m][2][e]);
                    const float og = sigmt(acc[m][3][e]);
                    const float cn = fg * c[m*4 + e] + ig * gg;
                    c[m*4 + e] = cn;
                    hv[j] = og * tanha(cn);

                    if (s == TT - 1)
                        out[sent_off + (size_t)(b0 + row) * 128 + dir*64 + kkg + j] = hv[j];

                    if (s & 1){
                        const int tlo = dir ? t : t - 1;
                        const float2 v = dir ? make_float2(hv[j], hprev[m*4 + e])
                                             : make_float2(hprev[m*4 + e], hv[j]);
                        *(float2*)&out[(size_t)(b0 + row) * (128*TT)
                                       + (dir*64 + kkg + j) * TT + tlo] = v;
                    } else {
                        hprev[m*4 + e] = hv[j];
                    }
                }
                const __half h0h = __float2half_rn(hv[0]);
                const __half h1h = __float2half_rn(hv[1]);
                const __half l0h = __float2half_rn(hv[0] - __half2float(h0h));
                const __half l1h = __float2half_rn(hv[1] - __half2float(h1h));
                const uint32_t soff = (uint32_t)(row * HP + kkg) * 2;
                *(uint32_t*)(sm + (nHi - smb) + soff) = pk2h(h0h, h1h);
                *(uint32_t*)(sm + (nLo - smb) + soff) = pk2h(l0h, l1h);
            }
        }
    }

    if (tid == 0 && blockIdx.x == 0 && blockIdx.y == 0)
        g_gen += 1;
}

// ============================================================================
extern "C" void kernel_launch(void* const* d_in, const int* in_sizes, int n_in,
                              void* d_out, int out_size)
{
    const int*   captions = (const int*)  d_in[0];
    const float* h0f = (const float*)d_in[2];
    const float* c0f = (const float*)d_in[3];
    const float* h0b = (const float*)d_in[4];
    const float* c0b = (const float*)d_in[5];
    const float* E   = (const float*)d_in[6];
    const float* Wf  = (const float*)d_in[7];
    const float* Uf  = (const float*)d_in[8];
    const float* bf  = (const float*)d_in[9];
    const float* Wb  = (const float*)d_in[10];
    const float* Ub  = (const float*)d_in[11];
    const float* bb  = (const float*)d_in[12];
    float* out = (float*)d_out;

    cudaFuncSetAttribute(gemm_tc,    cudaFuncAttributeMaxDynamicSharedMemorySize, G_SMEM);
    cudaFuncSetAttribute(lstm_fused, cudaFuncAttributeMaxDynamicSharedMemorySize, L_SMEM);

    // launch index:   0          1           2        3 (<- ncu capture)
    dd_markw  <<<640, 256>>>(captions, Wf, Wb);
    dd_compact<<<NBLK, 256>>>();

    dim3 gg(4, (NTOK + 127) / 128);
    gemm_tc<<<gg, 256, G_SMEM>>>(E);

    dim3 gl(BATCH / 64, 2);
    lstm_fused<<<gl, 512, L_SMEM>>>(captions, h0f, c0f, h0b, c0b,
                                    Uf, bf, Ub, bb, out);
}

// round 16
// speedup vs baseline: 1.6086x; 1.0765x over previous
#include <cuda_runtime.h>
#include <cuda_fp16.h>
#include <cstdint>

#define NTOK  50257
#define NIN   300
#define KPAD  320
#define TT    18
#define BATCH 4096
#define NCAP  (BATCH * TT)
#define NBLK  197              // ceil(NTOK/256)

typedef unsigned long long ull;

// ---------------- device scratch (no allocations allowed) ----------------
__device__ __half  g_EW [(size_t)NTOK * 512];   // fp16 [slot][dir*256 + gate*64 + kk]
__device__ __half  g_Wh [(size_t)512 * KPAD];   // [n][k], fp16
__device__ int g_flag[NTOK];    // generation-stamped presence flags
__device__ int g_list[NTOK];
__device__ int g_slot[NTOK];
__device__ int g_count;
__device__ int g_gen;           // increments once per kernel_launch (in lstm)

// ---------------- activation helpers ----------------
__device__ __forceinline__ float tanha(float x){
    float r; asm("tanh.approx.f32 %0, %1;" : "=f"(r) : "f"(x)); return r;
}
__device__ __forceinline__ float sigmt(float x){   // 0.5 + 0.5*tanh(x/2)
    return fmaf(tanha(x * 0.5f), 0.5f, 0.5f);
}

// ---------------- mma.sync helpers ----------------
__device__ __forceinline__ uint32_t smem_u32(const void* p){
    uint32_t a; asm("{ .reg .u64 t; cvta.to.shared.u64 t, %1; cvt.u32.u64 %0, t; }" : "=r"(a) : "l"(p));
    return a;
}
__device__ __forceinline__ void ldm4(uint32_t (&r)[4], uint32_t addr){
    asm volatile("ldmatrix.sync.aligned.m8n8.x4.shared.b16 {%0,%1,%2,%3}, [%4];"
        : "=r"(r[0]), "=r"(r[1]), "=r"(r[2]), "=r"(r[3]) : "r"(addr));
}
__device__ __forceinline__ void ldm2(uint32_t& r0, uint32_t& r1, uint32_t addr){
    asm volatile("ldmatrix.sync.aligned.m8n8.x2.shared.b16 {%0,%1}, [%2];"
        : "=r"(r0), "=r"(r1) : "r"(addr));
}
__device__ __forceinline__ void mma16816(float (&c)[4], const uint32_t (&a)[4],
                                         uint32_t b0, uint32_t b1){
    asm volatile(
        "mma.sync.aligned.m16n8k16.row.col.f32.f16.f16.f32 "
        "{%0,%1,%2,%3}, {%4,%5,%6,%7}, {%8,%9}, {%0,%1,%2,%3};"
        : "+f"(c[0]), "+f"(c[1]), "+f"(c[2]), "+f"(c[3])
        : "r"(a[0]), "r"(a[1]), "r"(a[2]), "r"(a[3]), "r"(b0), "r"(b1));
}
__device__ __forceinline__ uint32_t pk2h(__half a, __half b){
    return (uint32_t)__half_as_ushort(a) | ((uint32_t)__half_as_ushort(b) << 16);
}

// ============================================================================
// dd_markw / dd_compact: generation-stamped token dedup (+ W fp16 convert)
// ============================================================================
__global__ void dd_markw(const int* __restrict__ cap,
                         const float* __restrict__ Wf, const float* __restrict__ Wb){
    const int idx = blockIdx.x * 256 + threadIdx.x;
    const int gen = g_gen + 1;
    if (idx < NCAP) g_flag[cap[idx]] = gen;
    if (idx == 0)   g_count = 0;
    if (idx < 512 * KPAD){
        const int n = idx / KPAD, k = idx % KPAD;
        float v = 0.f;
        if (k < NIN) v = (n < 256) ? Wf[(size_t)k * 256 + n] : Wb[(size_t)k * 256 + (n - 256)];
        g_Wh[(size_t)n * KPAD + k] = __float2half_rn(v);
    }
}
__global__ void dd_compact(){
    const int i = blockIdx.x * 256 + threadIdx.x;
    const int gen = g_gen + 1;
    if (i < NTOK && g_flag[i] == gen){
        int pos = atomicAdd(&g_count, 1);
        g_list[pos] = i;
        g_slot[i]   = pos;
    }
}

// ============================================================================
// gemm_tc v5 (R14 known-good, ~55us): single-term fp16 GEMM.
// ============================================================================
#define KT          10
#define MAT_BYTES   10240
#define STAGE_BYTES 20480
#define G_SMEM      (2 * STAGE_BYTES)

__global__ void __launch_bounds__(256, 2) gemm_tc(const float* __restrict__ E)
{
    const int cnt = g_count;
    const int m0  = blockIdx.y * 128;
    if (m0 >= cnt) return;

    extern __shared__ char sm[];
    const uint32_t smb = smem_u32(sm);
    const int tid = threadIdx.x, lane = tid & 31, wid = tid >> 5;
    const int slab = blockIdx.x;
    const int warp_m = (wid >> 2) * 64;
    const int warp_n = (wid & 3) * 32;

    const int erow = tid >> 1, eh = tid & 1;
    const int wn   = tid >> 1, wc = tid & 1;
    const int gm   = m0 + erow;
    const int tokE = (gm < cnt) ? g_list[gm] : g_list[0];
    const float* Ebase = E + (size_t)tokE * NIN;
    const __half* WHb  = g_Wh + (size_t)(slab * 128 + wn) * KPAD;

    float4 eR[4]; uint4 wR[2];

    auto LDGT = [&](int kt){
        const int k0 = kt * 32;
        #pragma unroll
        for (int j = 0; j < 4; j++){
            const int k = k0 + eh * 16 + j * 4;
            eR[j] = (k < NIN) ? *(const float4*)(Ebase + k)
                              : make_float4(0.f, 0.f, 0.f, 0.f);
        }
        wR[0] = *(const uint4*)(WHb + k0 + wc * 16);
        wR[1] = *(const uint4*)(WHb + k0 + wc * 16 + 8);
    };
    auto STST = [&](int s){
        char* base = sm + s * STAGE_BYTES;
        #pragma unroll
        for (int j = 0; j < 4; j++){
            const float4 v = eR[j];
            const int koff = eh * 16 + j * 4;
            *(uint2*)(base + erow * 80 + koff * 2) =
                make_uint2(pk2h(__float2half_rn(v.x), __float2half_rn(v.y)),
                           pk2h(__float2half_rn(v.z), __float2half_rn(v.w)));
        }
        *(uint4*)(base + MAT_BYTES + wn * 80 + wc * 32)      = wR[0];
        *(uint4*)(base + MAT_BYTES + wn * 80 + wc * 32 + 16) = wR[1];
    };

    float acc[4][4][4];
    #pragma unroll
    for (int a = 0; a < 4; a++)
        #pragma unroll
        for (int b = 0; b < 4; b++)
            #pragma unroll
            for (int r = 0; r < 4; r++) acc[a][b][r] = 0.f;

    const int aR = warp_m + (lane & 15);
    const int aC = (lane >> 4) * 8;
    const int bR = warp_n + (lane & 7) + ((lane >> 4) << 3);
    const int bC = ((lane >> 3) & 1) * 8;

    LDGT(0); STST(0); __syncthreads();

    #pragma unroll 1
    for (int kt = 0; kt < KT; ++kt){
        if (kt + 1 < KT) LDGT(kt + 1);
        const uint32_t sb = smb + (kt & 1) * STAGE_BYTES;

        auto DOKB = [&](int kb){
            uint32_t ah[4][4];
            #pragma unroll
            for (int fm = 0; fm < 4; fm++)
                ldm4(ah[fm], sb + (aR + fm*16) * 80 + (aC + kb) * 2);
            uint32_t bh[4][2];
            #pragma unroll
            for (int g = 0; g < 2; g++){
                uint32_t t[4];
                ldm4(t, sb + MAT_BYTES + (bR + g*16) * 80 + (bC + kb) * 2);
                bh[2*g][0] = t[0]; bh[2*g][1] = t[1]; bh[2*g+1][0] = t[2]; bh[2*g+1][1] = t[3];
            }
            #pragma unroll
            for (int fm = 0; fm < 4; fm++)
                #pragma unroll
                for (int fn = 0; fn < 4; fn++)
                    mma16816(acc[fm][fn], ah[fm], bh[fn][0], bh[fn][1]);
        };
        DOKB(0);
        if (kt < KT - 1) DOKB(16);

        if (kt + 1 < KT) STST((kt + 1) & 1);
        __syncthreads();
    }

    const int rBase = m0 + warp_m + (lane >> 2);
    const int cBase = slab * 128 + warp_n + (lane & 3) * 2;
    #pragma unroll
    for (int fm = 0; fm < 4; fm++)
        #pragma unroll
        for (int fn = 0; fn < 4; fn++){
            const int r0 = rBase + fm * 16;
            const int cc = cBase + fn * 8;
            if (r0 < cnt)
                *(__half2*)&g_EW[(size_t)r0 * 512 + cc] =
                    __floats2half2_rn(acc[fm][fn][0], acc[fm][fn][1]);
            if (r0 + 8 < cnt)
                *(__half2*)&g_EW[(size_t)(r0 + 8) * 512 + cc] =
                    __floats2half2_rn(acc[fm][fn][2], acc[fm][fn][3]);
        }
}

// ============================================================================
// LSTM v13 — 32 batch rows / 256 threads / 8 warps, 2 CTAs per SM.
// Warp w = kk octet; each warp covers all 32 rows (two 16-row M tiles).
// 2-term recurrence z = (h_hi + h_lo) @ U_hi; fp16 EW gather.
// ============================================================================
#define LR      32                      // rows per CTA
#define HP      72
#define UTH_OFF 0
#define H_OFF   36864                   // U^T hi only
#define H_PL    (LR * HP * 2)           // 4608
#define TOK_OFF (H_OFF + 4 * H_PL)      // 55296
#define L_SMEM  (TOK_OFF + LR * TT * 4) // 57600  (x2 CTA = 115200)

__global__ void __launch_bounds__(256, 2) lstm_fused(
    const int*   __restrict__ cap,
    const float* __restrict__ h0f, const float* __restrict__ c0f,
    const float* __restrict__ h0b, const float* __restrict__ c0b,
    const float* __restrict__ Uf,  const float* __restrict__ bf,
    const float* __restrict__ Ub,  const float* __restrict__ bb,
    float* __restrict__ out)
{
    extern __shared__ char sm[];
    const uint32_t smb = smem_u32(sm);
    __half* UTH = (__half*)(sm + UTH_OFF);
    int (*toks)[TT] = (int(*)[TT])(sm + TOK_OFF);

    const int dir = blockIdx.y;
    const float* U  = dir ? Ub  : Uf;
    const float* bv = dir ? bb  : bf;
    const float* h0 = dir ? h0b : h0f;
    const float* c0 = dir ? c0b : c0f;
    const int b0   = blockIdx.x * LR;
    const int tid  = threadIdx.x;
    const int lane = tid & 31;
    const int wk   = tid >> 5;           // 0..7, kk octet

    // ---- prologue: U^T hi, tokens, h0 hi/lo planes ----
    for (int idx = tid; idx < 64 * 256; idx += 256){
        const int kk = idx >> 8, n = idx & 255;
        UTH[n * HP + kk] = __float2half_rn(U[kk * 256 + n]);
    }
    for (int idx = tid; idx < LR * TT; idx += 256)
        toks[idx / TT][idx % TT] = g_slot[cap[b0 * TT + idx]];
    {
        __half* Hhi = (__half*)(sm + H_OFF);
        __half* Hlo = (__half*)(sm + H_OFF + H_PL);
        for (int idx = tid; idx < LR * 64; idx += 256){
            const int r = idx >> 6, kk = idx & 63;
            const float v = h0[(size_t)(b0 + r) * 64 + kk];
            const __half hi = __float2half_rn(v);
            Hhi[r * HP + kk] = hi;
            Hlo[r * HP + kk] = __float2half_rn(v - __half2float(hi));
        }
    }

    const int kkg = wk * 8 + (lane & 3) * 2;
    float c[8];
    #pragma unroll
    for (int m = 0; m < 2; m++)
        #pragma unroll
        for (int r = 0; r < 2; r++)
            #pragma unroll
            for (int j = 0; j < 2; j++){
                const int row = m * 16 + (lane >> 2) + r * 8;
                c[m*4 + r*2 + j] = c0[(size_t)(b0 + row) * 64 + kkg + j];
            }
    float bias[4][2];
    #pragma unroll
    for (int g = 0; g < 4; g++){
        bias[g][0] = bv[g * 64 + kkg];
        bias[g][1] = bv[g * 64 + kkg + 1];
    }
    __syncthreads();

    // ---- U fragments (hi only): register-resident ----
    uint32_t uh[4][4][2];
    #pragma unroll
    for (int g = 0; g < 4; g++)
        #pragma unroll
        for (int kt = 0; kt < 4; kt++){
            const uint32_t off =
                (uint32_t)((g*64 + wk*8 + (lane & 7)) * HP + kt*16 + ((lane >> 3) & 1) * 8) * 2;
            ldm2(uh[g][kt][0], uh[g][kt][1], smb + UTH_OFF + off);
        }

    const size_t sent_off = (size_t)BATCH * 128 * TT;
    const int aR = lane & 15;
    const int aC = (lane >> 4) * 8;
    float hprev[8];

    for (int s = 0; s < TT; ++s){
        __syncthreads();
        const int t = dir ? (TT - 1 - s) : s;
        const int p = s & 1;
        const uint32_t hHi = smb + H_OFF + (p*2 + 0) * H_PL;
        const uint32_t hLo = smb + H_OFF + (p*2 + 1) * H_PL;

        // acc init = fp16 EW gather + bias
        float acc[2][4][4];
        #pragma unroll
        for (int m = 0; m < 2; m++){
            #pragma unroll
            for (int r = 0; r < 2; r++){
                const int row  = m * 16 + (lane >> 2) + r * 8;
                const int slot = toks[row][t];
                const __half* ew = g_EW + (size_t)slot * 512 + dir * 256 + kkg;
                #pragma unroll
                for (int g = 0; g < 4; g++){
                    const __half2 e = *(const __half2*)(ew + g * 64);
                    acc[m][g][r*2 + 0] = __low2float(e)  + bias[g][0];
                    acc[m][g][r*2 + 1] = __high2float(e) + bias[g][1];
                }
            }
        }

        // z += (h_hi + h_lo) @ U_hi
        #pragma unroll
        for (int kt = 0; kt < 4; kt++){
            uint32_t ahi[2][4], alo[2][4];
            #pragma unroll
            for (int m = 0; m < 2; m++){
                const uint32_t off = (uint32_t)((aR + m*16) * HP + aC + kt*16) * 2;
                ldm4(ahi[m], hHi + off);
                ldm4(alo[m], hLo + off);
            }
            #pragma unroll
            for (int m = 0; m < 2; m++)
                #pragma unroll
                for (int g = 0; g < 4; g++){
                    mma16816(acc[m][g], ahi[m], uh[g][kt][0], uh[g][kt][1]);
                    mma16816(acc[m][g], alo[m], uh[g][kt][0], uh[g][kt][1]);
                }
        }

        // epilogue
        const uint32_t nHi = smb + H_OFF + ((p^1)*2 + 0) * H_PL;
        const uint32_t nLo = smb + H_OFF + ((p^1)*2 + 1) * H_PL;
        #pragma unroll
        for (int m = 0; m < 2; m++){
            #pragma unroll
            for (int r = 0; r < 2; r++){
                const int row = m * 16 + (lane >> 2) + r * 8;
                float hv[2];
                #pragma unroll
                for (int j = 0; j < 2; j++){
                    const int e = r*2 + j;
                    const float ig = sigmt(acc[m][0][e]);
                    const float fg = sigmt(acc[m][1][e]);
                    const float gg = tanha(acc[m][2][e]);
                    const float og = sigmt(acc[m][3][e]);
                    const float cn = fg * c[m*4 + e] + ig * gg;
                    c[m*4 + e] = cn;
                    hv[j] = og * tanha(cn);

                    if (s == TT - 1)
                        out[sent_off + (size_t)(b0 + row) * 128 + dir*64 + kkg + j] = hv[j];

                    if (s & 1){
                        const int tlo = dir ? t : t - 1;
                        const float2 v = dir ? make_float2(hv[j], hprev[m*4 + e])
                                             : make_float2(hprev[m*4 + e], hv[j]);
                        *(float2*)&out[(size_t)(b0 + row) * (128*TT)
                                       + (dir*64 + kkg + j) * TT + tlo] = v;
                    } else {
                        hprev[m*4 + e] = hv[j];
                    }
                }
                const __half h0h = __float2half_rn(hv[0]);
                const __half h1h = __float2half_rn(hv[1]);
                const __half l0h = __float2half_rn(hv[0] - __half2float(h0h));
                const __half l1h = __float2half_rn(hv[1] - __half2float(h1h));
                const uint32_t soff = (uint32_t)(row * HP + kkg) * 2;
                *(uint32_t*)(sm + (nHi - smb) + soff) = pk2h(h0h, h1h);
                *(uint32_t*)(sm + (nLo - smb) + soff) = pk2h(l0h, l1h);
            }
        }
    }

    if (tid == 0 && blockIdx.x == 0 && blockIdx.y == 0)
        g_gen += 1;
}

// ============================================================================
extern "C" void kernel_launch(void* const* d_in, const int* in_sizes, int n_in,
                              void* d_out, int out_size)
{
    const int*   captions = (const int*)  d_in[0];
    const float* h0f = (const float*)d_in[2];
    const float* c0f = (const float*)d_in[3];
    const float* h0b = (const float*)d_in[4];
    const float* c0b = (const float*)d_in[5];
    const float* E   = (const float*)d_in[6];
    const float* Wf  = (const float*)d_in[7];
    const float* Uf  = (const float*)d_in[8];
    const float* bf  = (const float*)d_in[9];
    const float* Wb  = (const float*)d_in[10];
    const float* Ub  = (const float*)d_in[11];
    const float* bb  = (const float*)d_in[12];
    float* out = (float*)d_out;

    cudaFuncSetAttribute(gemm_tc,    cudaFuncAttributeMaxDynamicSharedMemorySize, G_SMEM);
    cudaFuncSetAttribute(lstm_fused, cudaFuncAttributeMaxDynamicSharedMemorySize, L_SMEM);

    // launch index:   0          1           2        3 (<- ncu capture)
    dd_markw  <<<640, 256>>>(captions, Wf, Wb);
    dd_compact<<<NBLK, 256>>>();

    dim3 gg(4, (NTOK + 127) / 128);
    gemm_tc<<<gg, 256, G_SMEM>>>(E);

    dim3 gl(BATCH / LR, 2);
    lstm_fused<<<gl, 256, L_SMEM>>>(captions, h0f, c0f, h0b, c0b,
                                    Uf, bf, Ub, bb, out);
}

// round 17
// speedup vs baseline: 1.6706x; 1.0386x over previous
#include <cuda_runtime.h>
#include <cuda_fp16.h>
#include <cstdint>

#define NTOK  50257
#define NIN   300
#define KPAD  320
#define TT    18
#define BATCH 4096
#define NCAP  (BATCH * TT)
#define NBLK  197              // ceil(NTOK/256)

typedef unsigned long long ull;

// ---------------- device scratch (no allocations allowed) ----------------
__device__ __half  g_EW [(size_t)NTOK * 512];   // fp16 [slot][dir*256 + gate*64 + kk]
__device__ __half  g_Wh [(size_t)512 * KPAD];   // [n][k], fp16
__device__ int g_flag[NTOK];    // generation-stamped presence flags
__device__ int g_list[NTOK];
__device__ int g_slot[NTOK];
__device__ int g_count;
__device__ int g_gen;           // increments once per kernel_launch (in lstm)

// ---------------- activation helpers ----------------
__device__ __forceinline__ float tanha(float x){
    float r; asm("tanh.approx.f32 %0, %1;" : "=f"(r) : "f"(x)); return r;
}
__device__ __forceinline__ float sigmt(float x){   // 0.5 + 0.5*tanh(x/2)
    return fmaf(tanha(x * 0.5f), 0.5f, 0.5f);
}

// ---------------- mma.sync helpers ----------------
__device__ __forceinline__ uint32_t smem_u32(const void* p){
    uint32_t a; asm("{ .reg .u64 t; cvta.to.shared.u64 t, %1; cvt.u32.u64 %0, t; }" : "=r"(a) : "l"(p));
    return a;
}
__device__ __forceinline__ void ldm4(uint32_t (&r)[4], uint32_t addr){
    asm volatile("ldmatrix.sync.aligned.m8n8.x4.shared.b16 {%0,%1,%2,%3}, [%4];"
        : "=r"(r[0]), "=r"(r[1]), "=r"(r[2]), "=r"(r[3]) : "r"(addr));
}
__device__ __forceinline__ void ldm2(uint32_t& r0, uint32_t& r1, uint32_t addr){
    asm volatile("ldmatrix.sync.aligned.m8n8.x2.shared.b16 {%0,%1}, [%2];"
        : "=r"(r0), "=r"(r1) : "r"(addr));
}
__device__ __forceinline__ void mma16816(float (&c)[4], const uint32_t (&a)[4],
                                         uint32_t b0, uint32_t b1){
    asm volatile(
        "mma.sync.aligned.m16n8k16.row.col.f32.f16.f16.f32 "
        "{%0,%1,%2,%3}, {%4,%5,%6,%7}, {%8,%9}, {%0,%1,%2,%3};"
        : "+f"(c[0]), "+f"(c[1]), "+f"(c[2]), "+f"(c[3])
        : "r"(a[0]), "r"(a[1]), "r"(a[2]), "r"(a[3]), "r"(b0), "r"(b1));
}
__device__ __forceinline__ uint32_t pk2h(__half a, __half b){
    return (uint32_t)__half_as_ushort(a) | ((uint32_t)__half_as_ushort(b) << 16);
}

// ============================================================================
// dd_markw / dd_compact: generation-stamped token dedup (+ W fp16 convert)
// ============================================================================
__global__ void dd_markw(const int* __restrict__ cap,
                         const float* __restrict__ Wf, const float* __restrict__ Wb){
    const int idx = blockIdx.x * 256 + threadIdx.x;
    const int gen = g_gen + 1;
    if (idx < NCAP) g_flag[cap[idx]] = gen;
    if (idx == 0)   g_count = 0;
    if (idx < 512 * KPAD){
        const int n = idx / KPAD, k = idx % KPAD;
        float v = 0.f;
        if (k < NIN) v = (n < 256) ? Wf[(size_t)k * 256 + n] : Wb[(size_t)k * 256 + (n - 256)];
        g_Wh[(size_t)n * KPAD + k] = __float2half_rn(v);
    }
}
__global__ void dd_compact(){
    const int i = blockIdx.x * 256 + threadIdx.x;
    const int gen = g_gen + 1;
    if (i < NTOK && g_flag[i] == gen){
        int pos = atomicAdd(&g_count, 1);
        g_list[pos] = i;
        g_slot[i]   = pos;
    }
}

// ============================================================================
// gemm_tc v5 (known-good, ~55us): single-term fp16 GEMM.
// ============================================================================
#define KT          10
#define MAT_BYTES   10240
#define STAGE_BYTES 20480
#define G_SMEM      (2 * STAGE_BYTES)

__global__ void __launch_bounds__(256, 2) gemm_tc(const float* __restrict__ E)
{
    const int cnt = g_count;
    const int m0  = blockIdx.y * 128;
    if (m0 >= cnt) return;

    extern __shared__ char sm[];
    const uint32_t smb = smem_u32(sm);
    const int tid = threadIdx.x, lane = tid & 31, wid = tid >> 5;
    const int slab = blockIdx.x;
    const int warp_m = (wid >> 2) * 64;
    const int warp_n = (wid & 3) * 32;

    const int erow = tid >> 1, eh = tid & 1;
    const int wn   = tid >> 1, wc = tid & 1;
    const int gm   = m0 + erow;
    const int tokE = (gm < cnt) ? g_list[gm] : g_list[0];
    const float* Ebase = E + (size_t)tokE * NIN;
    const __half* WHb  = g_Wh + (size_t)(slab * 128 + wn) * KPAD;

    float4 eR[4]; uint4 wR[2];

    auto LDGT = [&](int kt){
        const int k0 = kt * 32;
        #pragma unroll
        for (int j = 0; j < 4; j++){
            const int k = k0 + eh * 16 + j * 4;
            eR[j] = (k < NIN) ? *(const float4*)(Ebase + k)
                              : make_float4(0.f, 0.f, 0.f, 0.f);
        }
        wR[0] = *(const uint4*)(WHb + k0 + wc * 16);
        wR[1] = *(const uint4*)(WHb + k0 + wc * 16 + 8);
    };
    auto STST = [&](int s){
        char* base = sm + s * STAGE_BYTES;
        #pragma unroll
        for (int j = 0; j < 4; j++){
            const float4 v = eR[j];
            const int koff = eh * 16 + j * 4;
            *(uint2*)(base + erow * 80 + koff * 2) =
                make_uint2(pk2h(__float2half_rn(v.x), __float2half_rn(v.y)),
                           pk2h(__float2half_rn(v.z), __float2half_rn(v.w)));
        }
        *(uint4*)(base + MAT_BYTES + wn * 80 + wc * 32)      = wR[0];
        *(uint4*)(base + MAT_BYTES + wn * 80 + wc * 32 + 16) = wR[1];
    };

    float acc[4][4][4];
    #pragma unroll
    for (int a = 0; a < 4; a++)
        #pragma unroll
        for (int b = 0; b < 4; b++)
            #pragma unroll
            for (int r = 0; r < 4; r++) acc[a][b][r] = 0.f;

    const int aR = warp_m + (lane & 15);
    const int aC = (lane >> 4) * 8;
    const int bR = warp_n + (lane & 7) + ((lane >> 4) << 3);
    const int bC = ((lane >> 3) & 1) * 8;

    LDGT(0); STST(0); __syncthreads();

    #pragma unroll 1
    for (int kt = 0; kt < KT; ++kt){
        if (kt + 1 < KT) LDGT(kt + 1);
        const uint32_t sb = smb + (kt & 1) * STAGE_BYTES;

        auto DOKB = [&](int kb){
            uint32_t ah[4][4];
            #pragma unroll
            for (int fm = 0; fm < 4; fm++)
                ldm4(ah[fm], sb + (aR + fm*16) * 80 + (aC + kb) * 2);
            uint32_t bh[4][2];
            #pragma unroll
            for (int g = 0; g < 2; g++){
                uint32_t t[4];
                ldm4(t, sb + MAT_BYTES + (bR + g*16) * 80 + (bC + kb) * 2);
                bh[2*g][0] = t[0]; bh[2*g][1] = t[1]; bh[2*g+1][0] = t[2]; bh[2*g+1][1] = t[3];
            }
            #pragma unroll
            for (int fm = 0; fm < 4; fm++)
                #pragma unroll
                for (int fn = 0; fn < 4; fn++)
                    mma16816(acc[fm][fn], ah[fm], bh[fn][0], bh[fn][1]);
        };
        DOKB(0);
        if (kt < KT - 1) DOKB(16);

        if (kt + 1 < KT) STST((kt + 1) & 1);
        __syncthreads();
    }

    const int rBase = m0 + warp_m + (lane >> 2);
    const int cBase = slab * 128 + warp_n + (lane & 3) * 2;
    #pragma unroll
    for (int fm = 0; fm < 4; fm++)
        #pragma unroll
        for (int fn = 0; fn < 4; fn++){
            const int r0 = rBase + fm * 16;
            const int cc = cBase + fn * 8;
            if (r0 < cnt)
                *(__half2*)&g_EW[(size_t)r0 * 512 + cc] =
                    __floats2half2_rn(acc[fm][fn][0], acc[fm][fn][1]);
            if (r0 + 8 < cnt)
                *(__half2*)&g_EW[(size_t)(r0 + 8) * 512 + cc] =
                    __floats2half2_rn(acc[fm][fn][2], acc[fm][fn][3]);
        }
}

// ============================================================================
// LSTM v14 — 32 rows / 256 threads / 8 warps, 2 CTAs per SM.
// SINGLE-term recurrence z = h_hi @ U_hi (h_lo dropped; error ledger ok).
// Per warp per step: 32 MMA + 8 ldm4 (halved from v13).
// ============================================================================
#define LR      32
#define HP      72
#define UTH_OFF 0
#define H_OFF   36864                   // h planes: [buf] x1 plane (hi only)
#define H_PL    (LR * HP * 2)           // 4608
#define TOK_OFF (H_OFF + 2 * H_PL)      // 46080
#define L_SMEM  (TOK_OFF + LR * TT * 4) // 48384  (x2 CTA = 96768)

__global__ void __launch_bounds__(256, 2) lstm_fused(
    const int*   __restrict__ cap,
    const float* __restrict__ h0f, const float* __restrict__ c0f,
    const float* __restrict__ h0b, const float* __restrict__ c0b,
    const float* __restrict__ Uf,  const float* __restrict__ bf,
    const float* __restrict__ Ub,  const float* __restrict__ bb,
    float* __restrict__ out)
{
    extern __shared__ char sm[];
    const uint32_t smb = smem_u32(sm);
    __half* UTH = (__half*)(sm + UTH_OFF);
    int (*toks)[TT] = (int(*)[TT])(sm + TOK_OFF);

    const int dir = blockIdx.y;
    const float* U  = dir ? Ub  : Uf;
    const float* bv = dir ? bb  : bf;
    const float* h0 = dir ? h0b : h0f;
    const float* c0 = dir ? c0b : c0f;
    const int b0   = blockIdx.x * LR;
    const int tid  = threadIdx.x;
    const int lane = tid & 31;
    const int wk   = tid >> 5;           // 0..7, kk octet

    // ---- prologue: U^T hi, tokens, h0 (hi plane only) ----
    for (int idx = tid; idx < 64 * 256; idx += 256){
        const int kk = idx >> 8, n = idx & 255;
        UTH[n * HP + kk] = __float2half_rn(U[kk * 256 + n]);
    }
    for (int idx = tid; idx < LR * TT; idx += 256)
        toks[idx / TT][idx % TT] = g_slot[cap[b0 * TT + idx]];
    {
        __half* Hhi = (__half*)(sm + H_OFF);
        for (int idx = tid; idx < LR * 64; idx += 256){
            const int r = idx >> 6, kk = idx & 63;
            Hhi[r * HP + kk] = __float2half_rn(h0[(size_t)(b0 + r) * 64 + kk]);
        }
    }

    const int kkg = wk * 8 + (lane & 3) * 2;
    float c[8];
    #pragma unroll
    for (int m = 0; m < 2; m++)
        #pragma unroll
        for (int r = 0; r < 2; r++)
            #pragma unroll
            for (int j = 0; j < 2; j++){
                const int row = m * 16 + (lane >> 2) + r * 8;
                c[m*4 + r*2 + j] = c0[(size_t)(b0 + row) * 64 + kkg + j];
            }
    float bias[4][2];
    #pragma unroll
    for (int g = 0; g < 4; g++){
        bias[g][0] = bv[g * 64 + kkg];
        bias[g][1] = bv[g * 64 + kkg + 1];
    }
    __syncthreads();

    // ---- U fragments (hi only): register-resident ----
    uint32_t uh[4][4][2];
    #pragma unroll
    for (int g = 0; g < 4; g++)
        #pragma unroll
        for (int kt = 0; kt < 4; kt++){
            const uint32_t off =
                (uint32_t)((g*64 + wk*8 + (lane & 7)) * HP + kt*16 + ((lane >> 3) & 1) * 8) * 2;
            ldm2(uh[g][kt][0], uh[g][kt][1], smb + UTH_OFF + off);
        }

    const size_t sent_off = (size_t)BATCH * 128 * TT;
    const int aR = lane & 15;
    const int aC = (lane >> 4) * 8;
    float hprev[8];

    for (int s = 0; s < TT; ++s){
        __syncthreads();
        const int t = dir ? (TT - 1 - s) : s;
        const int p = s & 1;
        const uint32_t hHi = smb + H_OFF + p * H_PL;

        // acc init = fp16 EW gather + bias
        float acc[2][4][4];
        #pragma unroll
        for (int m = 0; m < 2; m++){
            #pragma unroll
            for (int r = 0; r < 2; r++){
                const int row  = m * 16 + (lane >> 2) + r * 8;
                const int slot = toks[row][t];
                const __half* ew = g_EW + (size_t)slot * 512 + dir * 256 + kkg;
                #pragma unroll
                for (int g = 0; g < 4; g++){
                    const __half2 e = *(const __half2*)(ew + g * 64);
                    acc[m][g][r*2 + 0] = __low2float(e)  + bias[g][0];
                    acc[m][g][r*2 + 1] = __high2float(e) + bias[g][1];
                }
            }
        }

        // z += h_hi @ U_hi  (single term)
        #pragma unroll
        for (int kt = 0; kt < 4; kt++){
            uint32_t ahi[2][4];
            #pragma unroll
            for (int m = 0; m < 2; m++)
                ldm4(ahi[m], hHi + (uint32_t)((aR + m*16) * HP + aC + kt*16) * 2);
            #pragma unroll
            for (int m = 0; m < 2; m++)
                #pragma unroll
                for (int g = 0; g < 4; g++)
                    mma16816(acc[m][g], ahi[m], uh[g][kt][0], uh[g][kt][1]);
        }

        // epilogue
        const uint32_t nHi = smb + H_OFF + (p ^ 1) * H_PL;
        #pragma unroll
        for (int m = 0; m < 2; m++){
            #pragma unroll
            for (int r = 0; r < 2; r++){
                const int row = m * 16 + (lane >> 2) + r * 8;
                float hv[2];
                #pragma unroll
                for (int j = 0; j < 2; j++){
                    const int e = r*2 + j;
                    const float ig = sigmt(acc[m][0][e]);
                    const float fg = sigmt(acc[m][1][e]);
                    const float gg = tanha(acc[m][2][e]);
                    const float og = sigmt(acc[m][3][e]);
                    const float cn = fg * c[m*4 + e] + ig * gg;
                    c[m*4 + e] = cn;
                    hv[j] = og * tanha(cn);

                    if (s == TT - 1)
                        out[sent_off + (size_t)(b0 + row) * 128 + dir*64 + kkg + j] = hv[j];

                    if (s & 1){
                        const int tlo = dir ? t : t - 1;
                        const float2 v = dir ? make_float2(hv[j], hprev[m*4 + e])
                                             : make_float2(hprev[m*4 + e], hv[j]);
                        *(float2*)&out[(size_t)(b0 + row) * (128*TT)
                                       + (dir*64 + kkg + j) * TT + tlo] = v;
                    } else {
                        hprev[m*4 + e] = hv[j];
                    }
                }
                *(uint32_t*)(sm + (nHi - smb) + (uint32_t)(row * HP + kkg) * 2) =
                    pk2h(__float2half_rn(hv[0]), __float2half_rn(hv[1]));
            }
        }
    }

    if (tid == 0 && blockIdx.x == 0 && blockIdx.y == 0)
        g_gen += 1;
}

// ============================================================================
extern "C" void kernel_launch(void* const* d_in, const int* in_sizes, int n_in,
                              void* d_out, int out_size)
{
    const int*   captions = (const int*)  d_in[0];
    const float* h0f = (const float*)d_in[2];
    const float* c0f = (const float*)d_in[3];
    const float* h0b = (const float*)d_in[4];
    const float* c0b = (const float*)d_in[5];
    const float* E   = (const float*)d_in[6];
    const float* Wf  = (const float*)d_in[7];
    const float* Uf  = (const float*)d_in[8];
    const float* bf  = (const float*)d_in[9];
    const float* Wb  = (const float*)d_in[10];
    const float* Ub  = (const float*)d_in[11];
    const float* bb  = (const float*)d_in[12];
    float* out = (float*)d_out;

    cudaFuncSetAttribute(gemm_tc,    cudaFuncAttributeMaxDynamicSharedMemorySize, G_SMEM);
    cudaFuncSetAttribute(lstm_fused, cudaFuncAttributeMaxDynamicSharedMemorySize, L_SMEM);

    // launch index:   0          1           2        3 (<- ncu capture)
    dd_markw  <<<640, 256>>>(captions, Wf, Wb);
    dd_compact<<<NBLK, 256>>>();

    dim3 gg(4, (NTOK + 127) / 128);
    gemm_tc<<<gg, 256, G_SMEM>>>(E);

    dim3 gl(BATCH / LR, 2);
    lstm_fused<<<gl, 256, L_SMEM>>>(captions, h0f, c0f, h0b, c0b,
                                    Uf, bf, Ub, bb, out);
}